// round 1
// baseline (speedup 1.0000x reference)
#include <cuda_runtime.h>
#include <math.h>

#define NATOMS 1000
#define NPAIRS 10000
#define FDIM   64
#define NSH    9
#define NL     3
#define NRBF   20
#define NITER  2
#define CUTOFF 5.0f
#define MAXCG  320
#define NSLOT  4

// ---------------- device scratch (static; no allocations) ----------------
__device__ float g_Y[NPAIRS * NSH];
__device__ float g_Wij[NITER * NPAIRS * NL * FDIM];
__device__ float g_dx[NATOMS * NSH * FDIM];
__device__ int   g_ncg;
__device__ int   g_off[NSH + 1];
__device__ float g_cgv[MAXCG];
__device__ int   g_cgi[MAXCG];   // i2 | i3<<4 | l(i3)<<8

__device__ __forceinline__ int l_of(int r) { return (r >= 4) ? 2 : ((r >= 1) ? 1 : 0); }

// ---------------- CG table construction (fp32, matches reference) --------
__device__ __forceinline__ float ffact(int n) {
    const float f[9] = {1.f, 1.f, 2.f, 6.f, 24.f, 120.f, 720.f, 5040.f, 40320.f};
    return f[n];
}

__device__ float cg_complex(int l1, int m1, int l2, int m2, int l3, int m3) {
    if (m3 != m1 + m2) return 0.f;
    int lmin = (l1 > l2) ? l1 - l2 : l2 - l1;
    if (l3 < lmin || l3 > l1 + l2) return 0.f;
    float pre = sqrtf((2.f * l3 + 1.f) * ffact(l3 + l1 - l2) * ffact(l3 - l1 + l2) *
                      ffact(l1 + l2 - l3) / ffact(l1 + l2 + l3 + 1));
    pre *= sqrtf(ffact(l3 + m3) * ffact(l3 - m3) * ffact(l1 - m1) * ffact(l1 + m1) *
                 ffact(l2 - m2) * ffact(l2 + m2));
    float s = 0.f;
    for (int k = 0; k <= l1 + l2 - l3; k++) {
        int d2 = l1 - m1 - k, d3 = l2 + m2 - k, d4 = l3 - l2 + m1 + k, d5 = l3 - l1 - m2 + k;
        if (d2 < 0 || d3 < 0 || d4 < 0 || d5 < 0) continue;
        float denom = ffact(k) * ffact(l1 + l2 - l3 - k) * ffact(d2) * ffact(d3) *
                      ffact(d4) * ffact(d5);
        s += ((k & 1) ? -1.f : 1.f) / denom;
    }
    return pre * s;
}

struct USup { int n; int col[2]; float re[2], im[2]; };

__device__ USup usup(int r) {
    USup s;
    int l = l_of(r);
    int base = l * l + l;
    int mr = r - base;
    const float inv2 = 0.70710678118654752440f;
    if (mr == 0) {
        s.n = 1; s.col[0] = base; s.re[0] = 1.f; s.im[0] = 0.f;
    } else if (mr > 0) {
        int m = mr; float sg = (m & 1) ? -1.f : 1.f;
        s.n = 2;
        s.col[0] = base - m; s.re[0] = inv2;      s.im[0] = 0.f;
        s.col[1] = base + m; s.re[1] = sg * inv2; s.im[1] = 0.f;
    } else {
        int m = -mr; float sg = (m & 1) ? -1.f : 1.f;
        s.n = 2;
        s.col[0] = base - m; s.re[0] = 0.f; s.im[0] = inv2;
        s.col[1] = base + m; s.re[1] = 0.f; s.im[1] = -sg * inv2;
    }
    return s;
}

__global__ void cg_init_kernel() {
    __shared__ float dense[729];
    int t = threadIdx.x;
    if (t < 729) {
        int i1 = t / 81, i2 = (t / 9) % 9, i3 = t % 9;
        // final[i1,i2,i3] = Re(before[a=i2, b=i3, c=i1]), parity mask on (a,b,c)
        int a = i2, b = i3, c = i1;
        float out = 0.f;
        if (((l_of(a) + l_of(b) + l_of(c)) & 1) == 0) {
            USup Ua = usup(a), Ub = usup(b), Uc = usup(c);
            int la = l_of(a), lb = l_of(b), lc = l_of(c);
            int ba = la * la + la, bb = lb * lb + lb, bc = lc * lc + lc;
            float vre = 0.f;
            for (int i = 0; i < Ua.n; i++)
                for (int j = 0; j < Ub.n; j++)
                    for (int k = 0; k < Uc.n; k++) {
                        float cg = cg_complex(la, Ua.col[i] - ba, lb, Ub.col[j] - bb,
                                              lc, Uc.col[k] - bc);
                        if (cg == 0.f) continue;
                        float t1r = Ua.re[i] * Ub.re[j] - Ua.im[i] * Ub.im[j];
                        float t1i = Ua.re[i] * Ub.im[j] + Ua.im[i] * Ub.re[j];
                        // * conj(Uc) : real part
                        float tre = t1r * Uc.re[k] + t1i * Uc.im[k];
                        vre += cg * tre;
                    }
            if (fabsf(vre) > 1e-4f) out = vre;
        }
        dense[t] = out;
    }
    __syncthreads();
    if (t == 0) {
        int cnt = 0;
        for (int o = 0; o < NSH; o++) {
            g_off[o] = cnt;
            for (int i2 = 0; i2 < NSH; i2++)
                for (int i3 = 0; i3 < NSH; i3++) {
                    float v = dense[o * 81 + i2 * 9 + i3];
                    if (v != 0.f && cnt < MAXCG) {
                        g_cgv[cnt] = v;
                        g_cgi[cnt] = i2 | (i3 << 4) | (l_of(i3) << 8);
                        cnt++;
                    }
                }
        }
        g_off[NSH] = cnt;
        g_ncg = cnt;
    }
}

// ---------------- per-pair setup: Y, radial filter Wij for both t ---------
__global__ void pair_setup_kernel(const float* __restrict__ r_ij,
                                  const float* __restrict__ Wf,
                                  const float* __restrict__ bf) {
    int p = blockIdx.x * 4 + (threadIdx.x >> 6);
    int f = threadIdx.x & 63;
    if (p >= NPAIRS) return;
    float rx = r_ij[3 * p], ry = r_ij[3 * p + 1], rz = r_ij[3 * p + 2];
    float d = sqrtf(rx * rx + ry * ry + rz * rz);
    float inv = 1.f / d;
    float x = rx * inv, y = ry * inv, z = rz * inv;
    if (f < NSH) {
        const float c0 = 0.28209479177387814f;
        const float c1 = 0.4886025119029199f;
        const float c2 = 1.0925484305920792f;
        const float c3 = 0.31539156525252005f;
        const float c4 = 0.5462742152960396f;
        float Y;
        switch (f) {
            case 0: Y = c0; break;
            case 1: Y = c1 * y; break;
            case 2: Y = c1 * z; break;
            case 3: Y = c1 * x; break;
            case 4: Y = c2 * x * y; break;
            case 5: Y = c2 * y * z; break;
            case 6: Y = c3 * (3.f * z * z - 1.f); break;
            case 7: Y = c2 * x * z; break;
            default: Y = c4 * (x * x - y * y); break;
        }
        g_Y[p * NSH + f] = Y;
    }
    float rad[NRBF];
    const float width = CUTOFF / (NRBF - 1);
    const float alpha = -0.5f / (width * width);
    #pragma unroll
    for (int k = 0; k < NRBF; k++) {
        float dd = d - width * (float)k;   // offsets = linspace(0, CUTOFF, NRBF)
        rad[k] = __expf(alpha * dd * dd);
    }
    float cut = (d < CUTOFF) ? 0.5f * (cosf(d * (3.14159265358979323846f / CUTOFF)) + 1.f)
                             : 0.f;
    #pragma unroll
    for (int t = 0; t < NITER; t++) {
        #pragma unroll
        for (int l = 0; l < NL; l++) {
            float acc = bf[t * (NL * FDIM) + l * FDIM + f];
            #pragma unroll
            for (int k = 0; k < NRBF; k++)
                acc += rad[k] * Wf[t * NRBF * NL * FDIM + k * NL * FDIM + l * FDIM + f];
            g_Wij[((t * NPAIRS + p) * NL + l) * FDIM + f] = acc * cut;
        }
    }
}

// ---------------- x init: x[:,0,:] = emb[Z], rest zero --------------------
__global__ void x_init_kernel(const int* __restrict__ Z, const float* __restrict__ emb,
                              float* __restrict__ xout) {
    int i = blockIdx.x * blockDim.x + threadIdx.x;
    if (i >= NATOMS * NSH * FDIM) return;
    int f = i & 63;
    int o = (i >> 6) % NSH;
    int a = i / (NSH * FDIM);
    xout[i] = (o == 0) ? emb[Z[a] * FDIM + f] : 0.f;
}

// ---------------- message pass: atom-major, no atomics --------------------
__global__ __launch_bounds__(64 * NSLOT)
void msg_kernel(const int* __restrict__ idx_i, const int* __restrict__ idx_j,
                const float* __restrict__ x, int t) {
    __shared__ float s_xj[NSLOT][NSH * FDIM];
    __shared__ float s_coef[NSLOT][MAXCG];
    __shared__ float s_cgv[MAXCG];
    __shared__ int   s_cgi[MAXCG];
    __shared__ int   s_off[NSH + 1];

    int a = blockIdx.x;
    int tid = threadIdx.x;
    int f = tid & 63;
    int slot = tid >> 6;
    int ncg = g_ncg;
    for (int e = tid; e < ncg; e += blockDim.x) { s_cgv[e] = g_cgv[e]; s_cgi[e] = g_cgi[e]; }
    if (tid < NSH + 1) s_off[tid] = g_off[tid];

    // segment [pstart, pend) of sorted idx_i equal to a
    int lo = 0, hi = NPAIRS;
    while (lo < hi) { int m = (lo + hi) >> 1; if (idx_i[m] < a) lo = m + 1; else hi = m; }
    int pstart = lo;
    hi = NPAIRS;
    while (lo < hi) { int m = (lo + hi) >> 1; if (idx_i[m] <= a) lo = m + 1; else hi = m; }
    int pend = lo;
    __syncthreads();

    float yacc[NSH];
    #pragma unroll
    for (int o = 0; o < NSH; o++) yacc[o] = 0.f;

    int deg = pend - pstart;
    int nit = (deg + NSLOT - 1) / NSLOT;
    for (int it = 0; it < nit; it++) {
        int p = pstart + it * NSLOT + slot;
        bool valid = (p < pend);
        if (valid) {
            int j = idx_j[p];
            const float* xj = x + j * (NSH * FDIM);
            #pragma unroll
            for (int o = 0; o < NSH; o++) s_xj[slot][o * 64 + f] = xj[o * 64 + f];
            for (int e = f; e < ncg; e += 64) {
                int i3 = (s_cgi[e] >> 4) & 15;
                s_coef[slot][e] = s_cgv[e] * g_Y[p * NSH + i3];
            }
        }
        __syncthreads();
        if (valid) {
            const float* wp = g_Wij + ((t * NPAIRS + p) * NL) * FDIM + f;
            float w0 = wp[0], w1 = wp[64], w2 = wp[128];
            #pragma unroll
            for (int o = 0; o < NSH; o++) {
                float acc = 0.f;
                int e1 = s_off[o + 1];
                for (int e = s_off[o]; e < e1; e++) {
                    int pk = s_cgi[e];
                    int i2 = pk & 15;
                    int l = pk >> 8;
                    float w = (l == 0) ? w0 : ((l == 1) ? w1 : w2);
                    acc += s_coef[slot][e] * s_xj[slot][(i2 << 6) + f] * w;
                }
                yacc[o] += acc;
            }
        }
        __syncthreads();
    }
    // reduce slots
    #pragma unroll
    for (int o = 0; o < NSH; o++) s_xj[slot][o * 64 + f] = yacc[o];
    __syncthreads();
    for (int i = tid; i < NSH * FDIM; i += blockDim.x) {
        float s = s_xj[0][i] + s_xj[1][i] + s_xj[2][i] + s_xj[3][i];
        g_dx[a * (NSH * FDIM) + i] = s;
    }
}

// ---------------- per-atom update (W1, tp, W2, gate, W3, residual) -------
#define UPD_SMEM_WORDS (3 * 4096 + 12288 + 3 * 576 + MAXCG + MAXCG + 16)
#define UPD_SMEM_BYTES (UPD_SMEM_WORDS * 4)

__global__ __launch_bounds__(576)
void atom_update_kernel(float* __restrict__ xout,
                        const float* __restrict__ W1, const float* __restrict__ W2,
                        const float* __restrict__ W3, const float* __restrict__ Wg,
                        const float* __restrict__ bg, int t) {
    extern __shared__ float sm[];
    float* sW1 = sm;
    float* sW2 = sm + 4096;
    float* sW3 = sm + 8192;
    float* sWg = sm + 12288;          // 64 x 192
    float* sA  = sWg + 12288;         // 576
    float* sB  = sA + 576;
    float* sC  = sB + 576;
    float* s_cgv = sC + 576;
    int*   s_cgi = (int*)(s_cgv + MAXCG);
    int*   s_off = s_cgi + MAXCG;

    int tid = threadIdx.x;
    int o = tid >> 6;        // 0..8
    int f = tid & 63;
    int ncg = g_ncg;
    for (int i = tid; i < 4096; i += 576) {
        sW1[i] = W1[t * 4096 + i];
        sW2[i] = W2[t * 4096 + i];
        sW3[i] = W3[t * 4096 + i];
    }
    for (int i = tid; i < 12288; i += 576) sWg[i] = Wg[t * 12288 + i];
    for (int e = tid; e < ncg; e += 576) { s_cgv[e] = g_cgv[e]; s_cgi[e] = g_cgi[e]; }
    if (tid < NSH + 1) s_off[tid] = g_off[tid];
    __syncthreads();

    int l = (o >= 4) ? 2 : ((o >= 1) ? 1 : 0);
    float bgv = (o < 3) ? bg[t * 192 + o * 64 + f] : 0.f;

    for (int a = blockIdx.x; a < NATOMS; a += gridDim.x) {
        int base = a * (NSH * FDIM);
        float dxv = g_dx[base + o * 64 + f];
        sA[o * 64 + f] = dxv;
        __syncthreads();
        // ddx = dx @ W1
        float acc = 0.f;
        #pragma unroll 8
        for (int k = 0; k < 64; k++) acc += sA[o * 64 + k] * sW1[k * 64 + f];
        sB[o * 64 + f] = acc;
        __syncthreads();
        // tp[o] = sum_cg cg * dx[i2] * ddx[i3]  ; sum = dx + tp
        float tp = 0.f;
        int e1 = s_off[o + 1];
        for (int e = s_off[o]; e < e1; e++) {
            int pk = s_cgi[e];
            int i2 = pk & 15, i3 = (pk >> 4) & 15;
            tp += s_cgv[e] * sA[(i2 << 6) + f] * sB[(i3 << 6) + f];
        }
        sC[o * 64 + f] = dxv + tp;
        __syncthreads();
        // dx2 = (dx + tp) @ W2
        float acc2 = 0.f;
        #pragma unroll 8
        for (int k = 0; k < 64; k++) acc2 += sC[o * 64 + k] * sW2[k * 64 + f];
        sA[o * 64 + f] = acc2;
        __syncthreads();
        // gate = sigmoid(dx2[:,0] @ Wg + bg), per l
        if (o < 3) {
            float g = bgv;
            #pragma unroll 8
            for (int k = 0; k < 64; k++) g += sA[k] * sWg[k * 192 + o * 64 + f];
            sB[o * 64 + f] = 1.f / (1.f + __expf(-g));
        }
        __syncthreads();
        sC[o * 64 + f] = sA[o * 64 + f] * sB[l * 64 + f];
        __syncthreads();
        // dx3 = gated @ W3 ; x += dx3
        float acc3 = 0.f;
        #pragma unroll 8
        for (int k = 0; k < 64; k++) acc3 += sC[o * 64 + k] * sW3[k * 64 + f];
        xout[base + o * 64 + f] += acc3;
        __syncthreads();
    }
}

// ---------------- launch ---------------------------------------------------
extern "C" void kernel_launch(void* const* d_in, const int* in_sizes, int n_in,
                              void* d_out, int out_size) {
    const int*   Z    = (const int*)d_in[0];
    const float* r_ij = (const float*)d_in[1];
    const int*   idxi = (const int*)d_in[2];
    const int*   idxj = (const int*)d_in[3];
    const float* emb  = (const float*)d_in[4];
    const float* Wf   = (const float*)d_in[5];
    const float* bf   = (const float*)d_in[6];
    const float* W1   = (const float*)d_in[7];
    const float* W2   = (const float*)d_in[8];
    const float* W3   = (const float*)d_in[9];
    const float* Wg   = (const float*)d_in[10];
    const float* bg   = (const float*)d_in[11];
    float* xout = (float*)d_out;

    static bool attr_set = false;
    if (!attr_set) {
        cudaFuncSetAttribute(atom_update_kernel,
                             cudaFuncAttributeMaxDynamicSharedMemorySize, UPD_SMEM_BYTES);
        attr_set = true;
    }

    cg_init_kernel<<<1, 729>>>();
    pair_setup_kernel<<<(NPAIRS + 3) / 4, 256>>>(r_ij, Wf, bf);
    x_init_kernel<<<(NATOMS * NSH * FDIM + 255) / 256, 256>>>(Z, emb, xout);
    for (int t = 0; t < NITER; t++) {
        msg_kernel<<<NATOMS, 64 * NSLOT>>>(idxi, idxj, xout, t);
        atom_update_kernel<<<250, 576, UPD_SMEM_BYTES>>>(xout, W1, W2, W3, Wg, bg, t);
    }
}

// round 3
// speedup vs baseline: 2.2394x; 2.2394x over previous
#include <cuda_runtime.h>
#include <math.h>

#define NATOMS 1000
#define NPAIRS 10000
#define FDIM   64
#define NSH    9
#define NL     3
#define NRBF   20
#define NITER  2
#define CUTOFF 5.0f

#define HDC __host__ __device__

// ---------------- device scratch (static; no allocations) ----------------
__device__ float g_Y[NPAIRS * NSH];
__device__ float g_Wij[NITER * NPAIRS * NL * FDIM];
__device__ float g_dx[NATOMS * NSH * FDIM];

// =================== compile-time real Clebsch-Gordan table ===============
HDC constexpr double cfact(int n) { double r = 1; for (int i = 2; i <= n; i++) r *= i; return r; }
HDC constexpr double csqrt_(double x) {
    if (x <= 0.0) return 0.0;
    double g = (x > 1.0) ? x : 1.0;
    for (int i = 0; i < 64; i++) g = 0.5 * (g + x / g);
    return g;
}
HDC constexpr int lof(int r) { return r >= 4 ? 2 : (r >= 1 ? 1 : 0); }

HDC constexpr double cg_c(int l1, int m1, int l2, int m2, int l3, int m3) {
    if (m3 != m1 + m2) return 0.0;
    int lmin = (l1 > l2) ? l1 - l2 : l2 - l1;
    if (l3 < lmin || l3 > l1 + l2) return 0.0;
    double pre = csqrt_((2.0 * l3 + 1.0) * cfact(l3 + l1 - l2) * cfact(l3 - l1 + l2) *
                        cfact(l1 + l2 - l3) / cfact(l1 + l2 + l3 + 1));
    pre *= csqrt_(cfact(l3 + m3) * cfact(l3 - m3) * cfact(l1 - m1) * cfact(l1 + m1) *
                  cfact(l2 - m2) * cfact(l2 + m2));
    double s = 0.0;
    for (int k = 0; k <= l1 + l2 - l3; k++) {
        int d2 = l1 - m1 - k, d3 = l2 + m2 - k, d4 = l3 - l2 + m1 + k, d5 = l3 - l1 - m2 + k;
        if (d2 < 0 || d3 < 0 || d4 < 0 || d5 < 0) continue;
        double denom = cfact(k) * cfact(l1 + l2 - l3 - k) * cfact(d2) * cfact(d3) *
                       cfact(d4) * cfact(d5);
        s += ((k & 1) ? -1.0 : 1.0) / denom;
    }
    return pre * s;
}

struct CRow { int n; int col[2]; double re[2]; double im[2]; };

HDC constexpr CRow urow(int r) {
    CRow s{}; int l = lof(r); int base = l * l + l; int mr = r - base;
    const double inv2 = 0.70710678118654752440;
    if (mr == 0) { s.n = 1; s.col[0] = base; s.re[0] = 1.0; s.im[0] = 0.0; }
    else if (mr > 0) {
        int m = mr; double sg = (m & 1) ? -1.0 : 1.0;
        s.n = 2;
        s.col[0] = base - m; s.re[0] = inv2;      s.im[0] = 0.0;
        s.col[1] = base + m; s.re[1] = sg * inv2; s.im[1] = 0.0;
    } else {
        int m = -mr; double sg = (m & 1) ? -1.0 : 1.0;
        s.n = 2;
        s.col[0] = base - m; s.re[0] = 0.0; s.im[0] = inv2;
        s.col[1] = base + m; s.re[1] = 0.0; s.im[1] = -sg * inv2;
    }
    return s;
}

// table[o][i2][i3] = Re( sum_{ijk} U[i2,i] U[i3,j] conj(U[o,k]) cgc[i,j,k] ), parity masked
HDC constexpr double real_cg(int o, int i2, int i3) {
    if (((lof(o) + lof(i2) + lof(i3)) & 1) != 0) return 0.0;
    CRow Ua = urow(i2), Ub = urow(i3), Uc = urow(o);
    int la = lof(i2), lb = lof(i3), lc = lof(o);
    int ba = la * la + la, bb = lb * lb + lb, bc = lc * lc + lc;
    double vre = 0.0;
    for (int i = 0; i < Ua.n; i++)
        for (int j = 0; j < Ub.n; j++)
            for (int k = 0; k < Uc.n; k++) {
                double cg = cg_c(la, Ua.col[i] - ba, lb, Ub.col[j] - bb, lc, Uc.col[k] - bc);
                if (cg == 0.0) continue;
                double t1r = Ua.re[i] * Ub.re[j] - Ua.im[i] * Ub.im[j];
                double t1i = Ua.re[i] * Ub.im[j] + Ua.im[i] * Ub.re[j];
                double tre = t1r * Uc.re[k] + t1i * Uc.im[k];  // * conj(Uc), real part
                vre += cg * tre;
            }
    return vre;
}

// ---- register-array contraction: acc[o] += cg * a[i2] * b[i3], fully unrolled ----
template <int LO, int HI>
struct Seg {
    static __device__ __forceinline__ void run(float (&acc)[9], const float (&a)[9],
                                               const float (&b)[9]) {
        if constexpr (HI - LO == 1) {
            constexpr int O = LO / 81, I2 = (LO / 9) % 9, I3 = LO % 9;
            constexpr double v = real_cg(O, I2, I3);
            if constexpr (v > 1e-9 || v < -1e-9) {
                acc[O] = fmaf((float)v, a[I2] * b[I3], acc[O]);
            }
        } else {
            Seg<LO, (LO + HI) / 2>::run(acc, a, b);
            Seg<(LO + HI) / 2, HI>::run(acc, a, b);
        }
    }
};

// ---- shared-memory float4 variant for the per-atom tensor product --------
template <int LO, int HI>
struct SegTP {
    static __device__ __forceinline__ void run(float4& tp, const float* sA, const float* sB,
                                               int f4) {
        if constexpr (HI - LO == 1) {
            constexpr int O = LO / 81, I2 = (LO / 9) % 9, I3 = LO % 9;
            constexpr double v = real_cg(O, I2, I3);
            if constexpr (v > 1e-9 || v < -1e-9) {
                float4 av = *reinterpret_cast<const float4*>(sA + I2 * 64 + f4);
                float4 bv = *reinterpret_cast<const float4*>(sB + I3 * 64 + f4);
                float c = (float)v;
                tp.x = fmaf(c, av.x * bv.x, tp.x);
                tp.y = fmaf(c, av.y * bv.y, tp.y);
                tp.z = fmaf(c, av.z * bv.z, tp.z);
                tp.w = fmaf(c, av.w * bv.w, tp.w);
            }
        } else {
            SegTP<LO, (LO + HI) / 2>::run(tp, sA, sB, f4);
            SegTP<(LO + HI) / 2, HI>::run(tp, sA, sB, f4);
        }
    }
};

// ---------------- per-pair setup: Y, radial filter Wij for both t ---------
__global__ void pair_setup_kernel(const float* __restrict__ r_ij,
                                  const float* __restrict__ Wf,
                                  const float* __restrict__ bf) {
    int p = blockIdx.x * 4 + (threadIdx.x >> 6);
    int f = threadIdx.x & 63;
    if (p >= NPAIRS) return;
    float rx = r_ij[3 * p], ry = r_ij[3 * p + 1], rz = r_ij[3 * p + 2];
    float d = sqrtf(rx * rx + ry * ry + rz * rz);
    float inv = 1.f / d;
    float x = rx * inv, y = ry * inv, z = rz * inv;
    if (f < NSH) {
        const float c0 = 0.28209479177387814f;
        const float c1 = 0.4886025119029199f;
        const float c2 = 1.0925484305920792f;
        const float c3 = 0.31539156525252005f;
        const float c4 = 0.5462742152960396f;
        float Y;
        switch (f) {
            case 0: Y = c0; break;
            case 1: Y = c1 * y; break;
            case 2: Y = c1 * z; break;
            case 3: Y = c1 * x; break;
            case 4: Y = c2 * x * y; break;
            case 5: Y = c2 * y * z; break;
            case 6: Y = c3 * (3.f * z * z - 1.f); break;
            case 7: Y = c2 * x * z; break;
            default: Y = c4 * (x * x - y * y); break;
        }
        g_Y[p * NSH + f] = Y;
    }
    float rad[NRBF];
    const float width = CUTOFF / (NRBF - 1);
    const float alpha = -0.5f / (width * width);
    #pragma unroll
    for (int k = 0; k < NRBF; k++) {
        float dd = d - width * (float)k;
        rad[k] = __expf(alpha * dd * dd);
    }
    float cut = (d < CUTOFF) ? 0.5f * (cosf(d * (3.14159265358979323846f / CUTOFF)) + 1.f)
                             : 0.f;
    #pragma unroll
    for (int t = 0; t < NITER; t++) {
        #pragma unroll
        for (int l = 0; l < NL; l++) {
            float acc = bf[t * (NL * FDIM) + l * FDIM + f];
            #pragma unroll
            for (int k = 0; k < NRBF; k++)
                acc += rad[k] * Wf[t * NRBF * NL * FDIM + k * NL * FDIM + l * FDIM + f];
            g_Wij[((t * NPAIRS + p) * NL + l) * FDIM + f] = acc * cut;
        }
    }
}

// ---------------- x init: x[:,0,:] = emb[Z], rest zero --------------------
__global__ void x_init_kernel(const int* __restrict__ Z, const float* __restrict__ emb,
                              float* __restrict__ xout) {
    int i = blockIdx.x * blockDim.x + threadIdx.x;
    if (i >= NATOMS * NSH * FDIM) return;
    int f = i & 63;
    int o = (i >> 6) % NSH;
    int a = i / (NSH * FDIM);
    xout[i] = (o == 0) ? emb[Z[a] * FDIM + f] : 0.f;
}

// ---------------- message pass: atom-major, all-register TP ---------------
__global__ __launch_bounds__(256)
void msg_kernel(const int* __restrict__ idx_i, const int* __restrict__ idx_j,
                const float* __restrict__ x, int t) {
    int a = blockIdx.x * 4 + (threadIdx.x >> 6);
    int f = threadIdx.x & 63;
    if (a >= NATOMS) return;

    // segment [pstart, pend) of sorted idx_i equal to a
    int lo = 0, hi = NPAIRS;
    while (lo < hi) { int m = (lo + hi) >> 1; if (idx_i[m] < a) lo = m + 1; else hi = m; }
    int pstart = lo;
    hi = NPAIRS;
    while (lo < hi) { int m = (lo + hi) >> 1; if (idx_i[m] <= a) lo = m + 1; else hi = m; }
    int pend = lo;

    float acc[9];
    #pragma unroll
    for (int o = 0; o < 9; o++) acc[o] = 0.f;

    const float* wbase = g_Wij + (size_t)t * NPAIRS * NL * FDIM + f;

    for (int p = pstart; p < pend; p++) {
        int j = __ldg(idx_j + p);
        const float* xj = x + j * (NSH * FDIM) + f;
        float xr[9];
        #pragma unroll
        for (int o = 0; o < 9; o++) xr[o] = __ldg(xj + o * 64);
        float Yv[9];
        #pragma unroll
        for (int i = 0; i < 9; i++) Yv[i] = g_Y[p * NSH + i];
        const float* wp = wbase + p * (NL * FDIM);
        float w0 = wp[0], w1 = wp[64], w2 = wp[128];
        float tv[9];
        tv[0] = Yv[0] * w0;
        #pragma unroll
        for (int i = 1; i < 4; i++) tv[i] = Yv[i] * w1;
        #pragma unroll
        for (int i = 4; i < 9; i++) tv[i] = Yv[i] * w2;
        Seg<0, 729>::run(acc, xr, tv);
    }

    float* out = g_dx + a * (NSH * FDIM) + f;
    #pragma unroll
    for (int o = 0; o < 9; o++) out[o * 64] = acc[o];
}

// ---------------- per-atom update: float4 threads, weights via L1 ---------
__global__ __launch_bounds__(576)
void atom_update_kernel(float* __restrict__ xout,
                        const float* __restrict__ W1, const float* __restrict__ W2,
                        const float* __restrict__ W3, const float* __restrict__ Wg,
                        const float* __restrict__ bg, int t) {
    __shared__ float sA[4][576], sB[4][576], sC[4][576], sG[4][192];
    int tid = threadIdx.x;
    int slot = tid / 144;
    int r = tid % 144;
    int o = r / 16;
    int f4 = (r % 16) * 4;
    int a = blockIdx.x * 4 + slot;
    int l = o >= 4 ? 2 : (o >= 1 ? 1 : 0);

    const float* w1 = W1 + t * 4096;
    const float* w2 = W2 + t * 4096;
    const float* w3 = W3 + t * 4096;
    const float* wg = Wg + t * 12288;

    float4 bg4 = make_float4(0.f, 0.f, 0.f, 0.f);
    if (o < 3) bg4 = *reinterpret_cast<const float4*>(bg + t * 192 + o * 64 + f4);

    int base = a * (NSH * FDIM);
    float4 dx4 = *reinterpret_cast<const float4*>(g_dx + base + o * 64 + f4);
    *reinterpret_cast<float4*>(&sA[slot][o * 64 + f4]) = dx4;
    __syncthreads();

    // ddx = dx @ W1
    float4 acc = make_float4(0.f, 0.f, 0.f, 0.f);
    #pragma unroll
    for (int k = 0; k < 64; k++) {
        float av = sA[slot][o * 64 + k];
        float4 wv = *reinterpret_cast<const float4*>(w1 + k * 64 + f4);
        acc.x = fmaf(av, wv.x, acc.x); acc.y = fmaf(av, wv.y, acc.y);
        acc.z = fmaf(av, wv.z, acc.z); acc.w = fmaf(av, wv.w, acc.w);
    }
    *reinterpret_cast<float4*>(&sB[slot][o * 64 + f4]) = acc;
    __syncthreads();

    // tp[o] = sum cg * dx[i2]*ddx[i3] ; sC = dx + tp
    float4 tp = dx4;
    {
        const float* Ab = sA[slot];
        const float* Bb = sB[slot];
        switch (o) {
            case 0: SegTP<0,    81 >::run(tp, Ab, Bb, f4); break;
            case 1: SegTP<81,   162>::run(tp, Ab, Bb, f4); break;
            case 2: SegTP<162,  243>::run(tp, Ab, Bb, f4); break;
            case 3: SegTP<243,  324>::run(tp, Ab, Bb, f4); break;
            case 4: SegTP<324,  405>::run(tp, Ab, Bb, f4); break;
            case 5: SegTP<405,  486>::run(tp, Ab, Bb, f4); break;
            case 6: SegTP<486,  567>::run(tp, Ab, Bb, f4); break;
            case 7: SegTP<567,  648>::run(tp, Ab, Bb, f4); break;
            default: SegTP<648, 729>::run(tp, Ab, Bb, f4); break;
        }
    }
    *reinterpret_cast<float4*>(&sC[slot][o * 64 + f4]) = tp;
    __syncthreads();

    // dx2 = (dx + tp) @ W2
    float4 acc2 = make_float4(0.f, 0.f, 0.f, 0.f);
    #pragma unroll
    for (int k = 0; k < 64; k++) {
        float av = sC[slot][o * 64 + k];
        float4 wv = *reinterpret_cast<const float4*>(w2 + k * 64 + f4);
        acc2.x = fmaf(av, wv.x, acc2.x); acc2.y = fmaf(av, wv.y, acc2.y);
        acc2.z = fmaf(av, wv.z, acc2.z); acc2.w = fmaf(av, wv.w, acc2.w);
    }
    *reinterpret_cast<float4*>(&sA[slot][o * 64 + f4]) = acc2;
    __syncthreads();

    // gate = sigmoid(dx2[:,0] @ Wg + bg)
    if (o < 3) {
        float4 g = bg4;
        #pragma unroll
        for (int k = 0; k < 64; k++) {
            float av = sA[slot][k];
            float4 wv = *reinterpret_cast<const float4*>(wg + k * 192 + o * 64 + f4);
            g.x = fmaf(av, wv.x, g.x); g.y = fmaf(av, wv.y, g.y);
            g.z = fmaf(av, wv.z, g.z); g.w = fmaf(av, wv.w, g.w);
        }
        float4 s;
        s.x = 1.f / (1.f + __expf(-g.x));
        s.y = 1.f / (1.f + __expf(-g.y));
        s.z = 1.f / (1.f + __expf(-g.z));
        s.w = 1.f / (1.f + __expf(-g.w));
        *reinterpret_cast<float4*>(&sG[slot][o * 64 + f4]) = s;
    }
    __syncthreads();

    float4 gt = *reinterpret_cast<const float4*>(&sG[slot][l * 64 + f4]);
    float4 gated = make_float4(acc2.x * gt.x, acc2.y * gt.y, acc2.z * gt.z, acc2.w * gt.w);
    *reinterpret_cast<float4*>(&sC[slot][o * 64 + f4]) = gated;
    __syncthreads();

    // dx3 = gated @ W3 ; x += dx3
    float4 acc3 = make_float4(0.f, 0.f, 0.f, 0.f);
    #pragma unroll
    for (int k = 0; k < 64; k++) {
        float av = sC[slot][o * 64 + k];
        float4 wv = *reinterpret_cast<const float4*>(w3 + k * 64 + f4);
        acc3.x = fmaf(av, wv.x, acc3.x); acc3.y = fmaf(av, wv.y, acc3.y);
        acc3.z = fmaf(av, wv.z, acc3.z); acc3.w = fmaf(av, wv.w, acc3.w);
    }
    float4* xo = reinterpret_cast<float4*>(xout + base + o * 64 + f4);
    float4 xv = *xo;
    xv.x += acc3.x; xv.y += acc3.y; xv.z += acc3.z; xv.w += acc3.w;
    *xo = xv;
}

// ---------------- launch ---------------------------------------------------
extern "C" void kernel_launch(void* const* d_in, const int* in_sizes, int n_in,
                              void* d_out, int out_size) {
    const int*   Z    = (const int*)d_in[0];
    const float* r_ij = (const float*)d_in[1];
    const int*   idxi = (const int*)d_in[2];
    const int*   idxj = (const int*)d_in[3];
    const float* emb  = (const float*)d_in[4];
    const float* Wf   = (const float*)d_in[5];
    const float* bf   = (const float*)d_in[6];
    const float* W1   = (const float*)d_in[7];
    const float* W2   = (const float*)d_in[8];
    const float* W3   = (const float*)d_in[9];
    const float* Wg   = (const float*)d_in[10];
    const float* bg   = (const float*)d_in[11];
    float* xout = (float*)d_out;

    pair_setup_kernel<<<(NPAIRS + 3) / 4, 256>>>(r_ij, Wf, bf);
    x_init_kernel<<<(NATOMS * NSH * FDIM + 255) / 256, 256>>>(Z, emb, xout);
    for (int t = 0; t < NITER; t++) {
        msg_kernel<<<(NATOMS + 3) / 4, 256>>>(idxi, idxj, xout, t);
        atom_update_kernel<<<(NATOMS + 3) / 4, 576>>>(xout, W1, W2, W3, Wg, bg, t);
    }
}

// round 4
// speedup vs baseline: 2.7092x; 1.2098x over previous
#include <cuda_runtime.h>
#include <math.h>

#define NATOMS 1000
#define NPAIRS 10000
#define FDIM   64
#define NSH    9
#define NL     3
#define NRBF   20
#define NITER  2
#define CUTOFF 5.0f

#define HDC __host__ __device__

// ---------------- device scratch (static; no allocations) ----------------
__device__ float g_Y[NPAIRS * NSH];
__device__ float g_Wij[NITER * NPAIRS * NL * FDIM];
__device__ float g_dx[NATOMS * NSH * FDIM];

// =================== compile-time real Clebsch-Gordan table ===============
HDC constexpr double cfact(int n) { double r = 1; for (int i = 2; i <= n; i++) r *= i; return r; }
HDC constexpr double csqrt_(double x) {
    if (x <= 0.0) return 0.0;
    double g = (x > 1.0) ? x : 1.0;
    for (int i = 0; i < 64; i++) g = 0.5 * (g + x / g);
    return g;
}
HDC constexpr int lof(int r) { return r >= 4 ? 2 : (r >= 1 ? 1 : 0); }

HDC constexpr double cg_c(int l1, int m1, int l2, int m2, int l3, int m3) {
    if (m3 != m1 + m2) return 0.0;
    int lmin = (l1 > l2) ? l1 - l2 : l2 - l1;
    if (l3 < lmin || l3 > l1 + l2) return 0.0;
    double pre = csqrt_((2.0 * l3 + 1.0) * cfact(l3 + l1 - l2) * cfact(l3 - l1 + l2) *
                        cfact(l1 + l2 - l3) / cfact(l1 + l2 + l3 + 1));
    pre *= csqrt_(cfact(l3 + m3) * cfact(l3 - m3) * cfact(l1 - m1) * cfact(l1 + m1) *
                  cfact(l2 - m2) * cfact(l2 + m2));
    double s = 0.0;
    for (int k = 0; k <= l1 + l2 - l3; k++) {
        int d2 = l1 - m1 - k, d3 = l2 + m2 - k, d4 = l3 - l2 + m1 + k, d5 = l3 - l1 - m2 + k;
        if (d2 < 0 || d3 < 0 || d4 < 0 || d5 < 0) continue;
        double denom = cfact(k) * cfact(l1 + l2 - l3 - k) * cfact(d2) * cfact(d3) *
                       cfact(d4) * cfact(d5);
        s += ((k & 1) ? -1.0 : 1.0) / denom;
    }
    return pre * s;
}

struct CRow { int n; int col[2]; double re[2]; double im[2]; };

HDC constexpr CRow urow(int r) {
    CRow s{}; int l = lof(r); int base = l * l + l; int mr = r - base;
    const double inv2 = 0.70710678118654752440;
    if (mr == 0) { s.n = 1; s.col[0] = base; s.re[0] = 1.0; s.im[0] = 0.0; }
    else if (mr > 0) {
        int m = mr; double sg = (m & 1) ? -1.0 : 1.0;
        s.n = 2;
        s.col[0] = base - m; s.re[0] = inv2;      s.im[0] = 0.0;
        s.col[1] = base + m; s.re[1] = sg * inv2; s.im[1] = 0.0;
    } else {
        int m = -mr; double sg = (m & 1) ? -1.0 : 1.0;
        s.n = 2;
        s.col[0] = base - m; s.re[0] = 0.0; s.im[0] = inv2;
        s.col[1] = base + m; s.re[1] = 0.0; s.im[1] = -sg * inv2;
    }
    return s;
}

HDC constexpr double real_cg(int o, int i2, int i3) {
    if (((lof(o) + lof(i2) + lof(i3)) & 1) != 0) return 0.0;
    CRow Ua = urow(i2), Ub = urow(i3), Uc = urow(o);
    int la = lof(i2), lb = lof(i3), lc = lof(o);
    int ba = la * la + la, bb = lb * lb + lb, bc = lc * lc + lc;
    double vre = 0.0;
    for (int i = 0; i < Ua.n; i++)
        for (int j = 0; j < Ub.n; j++)
            for (int k = 0; k < Uc.n; k++) {
                double cg = cg_c(la, Ua.col[i] - ba, lb, Ub.col[j] - bb, lc, Uc.col[k] - bc);
                if (cg == 0.0) continue;
                double t1r = Ua.re[i] * Ub.re[j] - Ua.im[i] * Ub.im[j];
                double t1i = Ua.re[i] * Ub.im[j] + Ua.im[i] * Ub.re[j];
                double tre = t1r * Uc.re[k] + t1i * Uc.im[k];
                vre += cg * tre;
            }
    return vre;
}

// ---- register-array contraction: acc[o] += cg * a[i2] * b[i3], fully unrolled ----
template <int LO, int HI>
struct Seg {
    static __device__ __forceinline__ void run(float (&acc)[9], const float (&a)[9],
                                               const float (&b)[9]) {
        if constexpr (HI - LO == 1) {
            constexpr int O = LO / 81, I2 = (LO / 9) % 9, I3 = LO % 9;
            constexpr double v = real_cg(O, I2, I3);
            if constexpr (v > 1e-9 || v < -1e-9) {
                acc[O] = fmaf((float)v, a[I2] * b[I3], acc[O]);
            }
        } else {
            Seg<LO, (LO + HI) / 2>::run(acc, a, b);
            Seg<(LO + HI) / 2, HI>::run(acc, a, b);
        }
    }
};

// ---------------- per-pair setup: Y, radial filter Wij for both t ---------
__global__ void pair_setup_kernel(const float* __restrict__ r_ij,
                                  const float* __restrict__ Wf,
                                  const float* __restrict__ bf) {
    int p = blockIdx.x * 4 + (threadIdx.x >> 6);
    int f = threadIdx.x & 63;
    if (p >= NPAIRS) return;
    float rx = r_ij[3 * p], ry = r_ij[3 * p + 1], rz = r_ij[3 * p + 2];
    float d = sqrtf(rx * rx + ry * ry + rz * rz);
    float inv = 1.f / d;
    float x = rx * inv, y = ry * inv, z = rz * inv;
    if (f < NSH) {
        const float c0 = 0.28209479177387814f;
        const float c1 = 0.4886025119029199f;
        const float c2 = 1.0925484305920792f;
        const float c3 = 0.31539156525252005f;
        const float c4 = 0.5462742152960396f;
        float Y;
        switch (f) {
            case 0: Y = c0; break;
            case 1: Y = c1 * y; break;
            case 2: Y = c1 * z; break;
            case 3: Y = c1 * x; break;
            case 4: Y = c2 * x * y; break;
            case 5: Y = c2 * y * z; break;
            case 6: Y = c3 * (3.f * z * z - 1.f); break;
            case 7: Y = c2 * x * z; break;
            default: Y = c4 * (x * x - y * y); break;
        }
        g_Y[p * NSH + f] = Y;
    }
    float rad[NRBF];
    const float width = CUTOFF / (NRBF - 1);
    const float alpha = -0.5f / (width * width);
    #pragma unroll
    for (int k = 0; k < NRBF; k++) {
        float dd = d - width * (float)k;
        rad[k] = __expf(alpha * dd * dd);
    }
    float cut = (d < CUTOFF) ? 0.5f * (cosf(d * (3.14159265358979323846f / CUTOFF)) + 1.f)
                             : 0.f;
    #pragma unroll
    for (int t = 0; t < NITER; t++) {
        #pragma unroll
        for (int l = 0; l < NL; l++) {
            float acc = bf[t * (NL * FDIM) + l * FDIM + f];
            #pragma unroll
            for (int k = 0; k < NRBF; k++)
                acc += rad[k] * Wf[t * NRBF * NL * FDIM + k * NL * FDIM + l * FDIM + f];
            g_Wij[((t * NPAIRS + p) * NL + l) * FDIM + f] = acc * cut;
        }
    }
}

// ---------------- x init: x[:,0,:] = emb[Z], rest zero --------------------
__global__ void x_init_kernel(const int* __restrict__ Z, const float* __restrict__ emb,
                              float* __restrict__ xout) {
    int i = blockIdx.x * blockDim.x + threadIdx.x;
    if (i >= NATOMS * NSH * FDIM) return;
    int f = i & 63;
    int o = (i >> 6) % NSH;
    int a = i / (NSH * FDIM);
    xout[i] = (o == 0) ? emb[Z[a] * FDIM + f] : 0.f;
}

// ---------------- message pass: atom-major, all-register TP ---------------
__global__ __launch_bounds__(256)
void msg_kernel(const int* __restrict__ idx_i, const int* __restrict__ idx_j,
                const float* __restrict__ x, int t) {
    int a = blockIdx.x * 4 + (threadIdx.x >> 6);
    int f = threadIdx.x & 63;
    if (a >= NATOMS) return;

    int lo = 0, hi = NPAIRS;
    while (lo < hi) { int m = (lo + hi) >> 1; if (idx_i[m] < a) lo = m + 1; else hi = m; }
    int pstart = lo;
    hi = NPAIRS;
    while (lo < hi) { int m = (lo + hi) >> 1; if (idx_i[m] <= a) lo = m + 1; else hi = m; }
    int pend = lo;

    float acc[9];
    #pragma unroll
    for (int o = 0; o < 9; o++) acc[o] = 0.f;

    const float* wbase = g_Wij + (size_t)t * NPAIRS * NL * FDIM + f;

    for (int p = pstart; p < pend; p++) {
        int j = __ldg(idx_j + p);
        const float* xj = x + j * (NSH * FDIM) + f;
        float xr[9];
        #pragma unroll
        for (int o = 0; o < 9; o++) xr[o] = __ldg(xj + o * 64);
        float Yv[9];
        #pragma unroll
        for (int i = 0; i < 9; i++) Yv[i] = g_Y[p * NSH + i];
        const float* wp = wbase + p * (NL * FDIM);
        float w0 = wp[0], w1 = wp[64], w2 = wp[128];
        float tv[9];
        tv[0] = Yv[0] * w0;
        #pragma unroll
        for (int i = 1; i < 4; i++) tv[i] = Yv[i] * w1;
        #pragma unroll
        for (int i = 4; i < 9; i++) tv[i] = Yv[i] * w2;
        Seg<0, 729>::run(acc, xr, tv);
    }

    float* out = g_dx + a * (NSH * FDIM) + f;
    #pragma unroll
    for (int o = 0; o < 9; o++) out[o * 64] = acc[o];
}

// ---------------- per-atom update: thread=f, register GEMV + register TP ----
__global__ __launch_bounds__(256)
void atom_update_kernel(float* __restrict__ xout,
                        const float* __restrict__ W1, const float* __restrict__ W2,
                        const float* __restrict__ W3, const float* __restrict__ Wg,
                        const float* __restrict__ bg, int t) {
    __shared__ float sb0[4][NSH * FDIM];
    __shared__ float sb1[4][NSH * FDIM];

    int tid = threadIdx.x;
    int slot = tid >> 6;          // 0..3
    int f = tid & 63;
    int a = blockIdx.x * 4 + slot;

    const float* w1 = W1 + t * 4096 + f;
    const float* w2 = W2 + t * 4096 + f;
    const float* w3 = W3 + t * 4096 + f;
    const float* wg = Wg + t * 12288 + f;
    const float* bgp = bg + t * 192 + f;

    int base = a * (NSH * FDIM);

    // load dx into registers + buf0
    float dxr[9];
    #pragma unroll
    for (int o = 0; o < 9; o++) {
        dxr[o] = g_dx[base + o * 64 + f];
        sb0[slot][o * 64 + f] = dxr[o];
    }

    // preload W1 column f
    float w[64];
    #pragma unroll
    for (int k = 0; k < 64; k++) w[k] = __ldg(w1 + k * 64);
    __syncthreads();

    // ddx = dx @ W1   (activations via smem broadcast, weights in regs)
    float ddx[9];
    const float4* a0 = reinterpret_cast<const float4*>(sb0[slot]);
    #pragma unroll
    for (int o = 0; o < 9; o++) {
        float s = 0.f;
        #pragma unroll
        for (int k4 = 0; k4 < 16; k4++) {
            float4 v = a0[o * 16 + k4];
            s = fmaf(v.x, w[k4 * 4 + 0], s);
            s = fmaf(v.y, w[k4 * 4 + 1], s);
            s = fmaf(v.z, w[k4 * 4 + 2], s);
            s = fmaf(v.w, w[k4 * 4 + 3], s);
        }
        ddx[o] = s;
    }

    // tp = dx + CG(dx, ddx)  — pure register math
    float tp[9];
    #pragma unroll
    for (int o = 0; o < 9; o++) tp[o] = dxr[o];
    Seg<0, 729>::run(tp, dxr, ddx);

    #pragma unroll
    for (int o = 0; o < 9; o++) sb1[slot][o * 64 + f] = tp[o];

    // preload W2 column f (overlaps with barrier)
    #pragma unroll
    for (int k = 0; k < 64; k++) w[k] = __ldg(w2 + k * 64);
    __syncthreads();

    // dx2 = (dx + tp) @ W2
    float dx2[9];
    const float4* a1 = reinterpret_cast<const float4*>(sb1[slot]);
    #pragma unroll
    for (int o = 0; o < 9; o++) {
        float s = 0.f;
        #pragma unroll
        for (int k4 = 0; k4 < 16; k4++) {
            float4 v = a1[o * 16 + k4];
            s = fmaf(v.x, w[k4 * 4 + 0], s);
            s = fmaf(v.y, w[k4 * 4 + 1], s);
            s = fmaf(v.z, w[k4 * 4 + 2], s);
            s = fmaf(v.w, w[k4 * 4 + 3], s);
        }
        dx2[o] = s;
    }
    // publish dx2 row 0 (only row needed for the gate) into buf0
    sb0[slot][f] = dx2[0];
    __syncthreads();

    // gate[o3][f] = sigmoid(bg + sum_k dx2[0][k] * Wg[k][o3*64+f])
    float g0 = bgp[0], g1 = bgp[64], g2 = bgp[128];
    {
        const float4* r0 = reinterpret_cast<const float4*>(sb0[slot]);
        #pragma unroll
        for (int k4 = 0; k4 < 16; k4++) {
            float4 v = r0[k4];
            const float* wgk = wg + (k4 * 4) * 192;
            g0 = fmaf(v.x, __ldg(wgk), g0);
            g1 = fmaf(v.x, __ldg(wgk + 64), g1);
            g2 = fmaf(v.x, __ldg(wgk + 128), g2);
            g0 = fmaf(v.y, __ldg(wgk + 192), g0);
            g1 = fmaf(v.y, __ldg(wgk + 256), g1);
            g2 = fmaf(v.y, __ldg(wgk + 320), g2);
            g0 = fmaf(v.z, __ldg(wgk + 384), g0);
            g1 = fmaf(v.z, __ldg(wgk + 448), g1);
            g2 = fmaf(v.z, __ldg(wgk + 512), g2);
            g0 = fmaf(v.w, __ldg(wgk + 576), g0);
            g1 = fmaf(v.w, __ldg(wgk + 640), g1);
            g2 = fmaf(v.w, __ldg(wgk + 704), g2);
        }
    }
    float sg[3];
    sg[0] = 1.f / (1.f + __expf(-g0));
    sg[1] = 1.f / (1.f + __expf(-g1));
    sg[2] = 1.f / (1.f + __expf(-g2));

    // gated = dx2 * sigmoid(gate[l(o)])  — local; publish to buf1
    float gated[9];
    #pragma unroll
    for (int o = 0; o < 9; o++) {
        int l = (o >= 4) ? 2 : ((o >= 1) ? 1 : 0);
        gated[o] = dx2[o] * sg[l];
        sb1[slot][o * 64 + f] = gated[o];
    }

    // preload W3 column f
    #pragma unroll
    for (int k = 0; k < 64; k++) w[k] = __ldg(w3 + k * 64);
    __syncthreads();

    // dx3 = gated @ W3 ; x += dx3
    #pragma unroll
    for (int o = 0; o < 9; o++) {
        float s = 0.f;
        #pragma unroll
        for (int k4 = 0; k4 < 16; k4++) {
            float4 v = a1[o * 16 + k4];
            s = fmaf(v.x, w[k4 * 4 + 0], s);
            s = fmaf(v.y, w[k4 * 4 + 1], s);
            s = fmaf(v.z, w[k4 * 4 + 2], s);
            s = fmaf(v.w, w[k4 * 4 + 3], s);
        }
        xout[base + o * 64 + f] += s;
    }
}

// ---------------- launch ---------------------------------------------------
extern "C" void kernel_launch(void* const* d_in, const int* in_sizes, int n_in,
                              void* d_out, int out_size) {
    const int*   Z    = (const int*)d_in[0];
    const float* r_ij = (const float*)d_in[1];
    const int*   idxi = (const int*)d_in[2];
    const int*   idxj = (const int*)d_in[3];
    const float* emb  = (const float*)d_in[4];
    const float* Wf   = (const float*)d_in[5];
    const float* bf   = (const float*)d_in[6];
    const float* W1   = (const float*)d_in[7];
    const float* W2   = (const float*)d_in[8];
    const float* W3   = (const float*)d_in[9];
    const float* Wg   = (const float*)d_in[10];
    const float* bg   = (const float*)d_in[11];
    float* xout = (float*)d_out;

    pair_setup_kernel<<<(NPAIRS + 3) / 4, 256>>>(r_ij, Wf, bf);
    x_init_kernel<<<(NATOMS * NSH * FDIM + 255) / 256, 256>>>(Z, emb, xout);
    for (int t = 0; t < NITER; t++) {
        msg_kernel<<<(NATOMS + 3) / 4, 256>>>(idxi, idxj, xout, t);
        atom_update_kernel<<<(NATOMS + 3) / 4, 256>>>(xout, W1, W2, W3, Wg, bg, t);
    }
}

// round 5
// speedup vs baseline: 3.3766x; 1.2463x over previous
#include <cuda_runtime.h>
#include <math.h>

#define NATOMS 1000
#define NPAIRS 10000
#define FDIM   64
#define NSH    9
#define NL     3
#define NRBF   20
#define CUTOFF 5.0f
#define NITER  2

#define HDC __host__ __device__

// ---------------- device scratch (static; no allocations) ----------------
__device__ float g_Y[NPAIRS * NSH];
__device__ float g_Wij[NITER * NPAIRS * NL * FDIM];

// =================== compile-time real Clebsch-Gordan table ===============
HDC constexpr double cfact(int n) { double r = 1; for (int i = 2; i <= n; i++) r *= i; return r; }
HDC constexpr double csqrt_(double x) {
    if (x <= 0.0) return 0.0;
    double g = (x > 1.0) ? x : 1.0;
    for (int i = 0; i < 64; i++) g = 0.5 * (g + x / g);
    return g;
}
HDC constexpr int lof(int r) { return r >= 4 ? 2 : (r >= 1 ? 1 : 0); }

HDC constexpr double cg_c(int l1, int m1, int l2, int m2, int l3, int m3) {
    if (m3 != m1 + m2) return 0.0;
    int lmin = (l1 > l2) ? l1 - l2 : l2 - l1;
    if (l3 < lmin || l3 > l1 + l2) return 0.0;
    double pre = csqrt_((2.0 * l3 + 1.0) * cfact(l3 + l1 - l2) * cfact(l3 - l1 + l2) *
                        cfact(l1 + l2 - l3) / cfact(l1 + l2 + l3 + 1));
    pre *= csqrt_(cfact(l3 + m3) * cfact(l3 - m3) * cfact(l1 - m1) * cfact(l1 + m1) *
                  cfact(l2 - m2) * cfact(l2 + m2));
    double s = 0.0;
    for (int k = 0; k <= l1 + l2 - l3; k++) {
        int d2 = l1 - m1 - k, d3 = l2 + m2 - k, d4 = l3 - l2 + m1 + k, d5 = l3 - l1 - m2 + k;
        if (d2 < 0 || d3 < 0 || d4 < 0 || d5 < 0) continue;
        double denom = cfact(k) * cfact(l1 + l2 - l3 - k) * cfact(d2) * cfact(d3) *
                       cfact(d4) * cfact(d5);
        s += ((k & 1) ? -1.0 : 1.0) / denom;
    }
    return pre * s;
}

struct CRow { int n; int col[2]; double re[2]; double im[2]; };

HDC constexpr CRow urow(int r) {
    CRow s{}; int l = lof(r); int base = l * l + l; int mr = r - base;
    const double inv2 = 0.70710678118654752440;
    if (mr == 0) { s.n = 1; s.col[0] = base; s.re[0] = 1.0; s.im[0] = 0.0; }
    else if (mr > 0) {
        int m = mr; double sg = (m & 1) ? -1.0 : 1.0;
        s.n = 2;
        s.col[0] = base - m; s.re[0] = inv2;      s.im[0] = 0.0;
        s.col[1] = base + m; s.re[1] = sg * inv2; s.im[1] = 0.0;
    } else {
        int m = -mr; double sg = (m & 1) ? -1.0 : 1.0;
        s.n = 2;
        s.col[0] = base - m; s.re[0] = 0.0; s.im[0] = inv2;
        s.col[1] = base + m; s.re[1] = 0.0; s.im[1] = -sg * inv2;
    }
    return s;
}

HDC constexpr double real_cg(int o, int i2, int i3) {
    if (((lof(o) + lof(i2) + lof(i3)) & 1) != 0) return 0.0;
    CRow Ua = urow(i2), Ub = urow(i3), Uc = urow(o);
    int la = lof(i2), lb = lof(i3), lc = lof(o);
    int ba = la * la + la, bb = lb * lb + lb, bc = lc * lc + lc;
    double vre = 0.0;
    for (int i = 0; i < Ua.n; i++)
        for (int j = 0; j < Ub.n; j++)
            for (int k = 0; k < Uc.n; k++) {
                double cg = cg_c(la, Ua.col[i] - ba, lb, Ub.col[j] - bb, lc, Uc.col[k] - bc);
                if (cg == 0.0) continue;
                double t1r = Ua.re[i] * Ub.re[j] - Ua.im[i] * Ub.im[j];
                double t1i = Ua.re[i] * Ub.im[j] + Ua.im[i] * Ub.re[j];
                double tre = t1r * Uc.re[k] + t1i * Uc.im[k];
                vre += cg * tre;
            }
    return vre;
}

// ---- register-array contraction: acc[o] += cg * a[i2] * b[i3], fully unrolled ----
template <int LO, int HI>
struct Seg {
    static __device__ __forceinline__ void run(float (&acc)[9], const float (&a)[9],
                                               const float (&b)[9]) {
        if constexpr (HI - LO == 1) {
            constexpr int O = LO / 81, I2 = (LO / 9) % 9, I3 = LO % 9;
            constexpr double v = real_cg(O, I2, I3);
            if constexpr (v > 1e-9 || v < -1e-9) {
                acc[O] = fmaf((float)v, a[I2] * b[I3], acc[O]);
            }
        } else {
            Seg<LO, (LO + HI) / 2>::run(acc, a, b);
            Seg<(LO + HI) / 2, HI>::run(acc, a, b);
        }
    }
};

// diagonal coupling constants for i2 = 0 (scalar channel): cg(o, 0, o)
__device__ __constant__ const float C0DIAG_UNUSED = 0.f;  // placeholder
#define C0(o) ((float)real_cg(o, 0, o))

// ---------------- per-pair setup: Y, radial filter Wij for both t ---------
__global__ void pair_setup_kernel(const float* __restrict__ r_ij,
                                  const float* __restrict__ Wf,
                                  const float* __restrict__ bf) {
    int p = blockIdx.x * 4 + (threadIdx.x >> 6);
    int f = threadIdx.x & 63;
    if (p >= NPAIRS) return;
    float rx = r_ij[3 * p], ry = r_ij[3 * p + 1], rz = r_ij[3 * p + 2];
    float d = sqrtf(rx * rx + ry * ry + rz * rz);
    float inv = 1.f / d;
    float x = rx * inv, y = ry * inv, z = rz * inv;
    if (f < NSH) {
        const float c0 = 0.28209479177387814f;
        const float c1 = 0.4886025119029199f;
        const float c2 = 1.0925484305920792f;
        const float c3 = 0.31539156525252005f;
        const float c4 = 0.5462742152960396f;
        float Y;
        switch (f) {
            case 0: Y = c0; break;
            case 1: Y = c1 * y; break;
            case 2: Y = c1 * z; break;
            case 3: Y = c1 * x; break;
            case 4: Y = c2 * x * y; break;
            case 5: Y = c2 * y * z; break;
            case 6: Y = c3 * (3.f * z * z - 1.f); break;
            case 7: Y = c2 * x * z; break;
            default: Y = c4 * (x * x - y * y); break;
        }
        g_Y[p * NSH + f] = Y;
    }
    float rad[NRBF];
    const float width = CUTOFF / (NRBF - 1);
    const float alpha = -0.5f / (width * width);
    #pragma unroll
    for (int k = 0; k < NRBF; k++) {
        float dd = d - width * (float)k;
        rad[k] = __expf(alpha * dd * dd);
    }
    float cut = (d < CUTOFF) ? 0.5f * (cosf(d * (3.14159265358979323846f / CUTOFF)) + 1.f)
                             : 0.f;
    #pragma unroll
    for (int t = 0; t < NITER; t++) {
        #pragma unroll
        for (int l = 0; l < NL; l++) {
            float acc = bf[t * (NL * FDIM) + l * FDIM + f];
            #pragma unroll
            for (int k = 0; k < NRBF; k++)
                acc += rad[k] * Wf[t * NRBF * NL * FDIM + k * NL * FDIM + l * FDIM + f];
            g_Wij[((t * NPAIRS + p) * NL + l) * FDIM + f] = acc * cut;
        }
    }
}

// ---------------- fused message + update, one launch per interaction ------
template <bool FIRST>
__global__ __launch_bounds__(256)
void fused_kernel(const int* __restrict__ idx_i, const int* __restrict__ idx_j,
                  const int* __restrict__ Z, const float* __restrict__ emb,
                  float* __restrict__ xout,
                  const float* __restrict__ W1, const float* __restrict__ W2,
                  const float* __restrict__ W3, const float* __restrict__ Wg,
                  const float* __restrict__ bg) {
    constexpr int T = FIRST ? 0 : 1;
    __shared__ float sb0[4][NSH * FDIM];
    __shared__ float sb1[4][NSH * FDIM];

    int tid = threadIdx.x;
    int slot = tid >> 6;          // 0..3
    int f = tid & 63;
    int a = blockIdx.x * 4 + slot;

    // ---- segment of sorted idx_i equal to a ----
    int lo = 0, hi = NPAIRS;
    while (lo < hi) { int m = (lo + hi) >> 1; if (idx_i[m] < a) lo = m + 1; else hi = m; }
    int pstart = lo;
    hi = NPAIRS;
    while (lo < hi) { int m = (lo + hi) >> 1; if (idx_i[m] <= a) lo = m + 1; else hi = m; }
    int pend = lo;

    // ---- message pass: dx[a] accumulated in registers ----
    float dxr[9];
    #pragma unroll
    for (int o = 0; o < 9; o++) dxr[o] = 0.f;

    const float* wbase = g_Wij + (size_t)T * NPAIRS * NL * FDIM + f;

    for (int p = pstart; p < pend; p++) {
        int j = __ldg(idx_j + p);
        float Yv[9];
        #pragma unroll
        for (int i = 0; i < 9; i++) Yv[i] = g_Y[p * NSH + i];
        const float* wp = wbase + p * (NL * FDIM);
        float w0 = wp[0], w1v = wp[64], w2v = wp[128];
        float tv[9];
        tv[0] = Yv[0] * w0;
        #pragma unroll
        for (int i = 1; i < 4; i++) tv[i] = Yv[i] * w1v;
        #pragma unroll
        for (int i = 4; i < 9; i++) tv[i] = Yv[i] * w2v;

        if constexpr (FIRST) {
            // x[j] nonzero only at o=0 (scalar = emb[Z[j]]); cg(o,0,i3) = C0(o)*delta(o,i3)
            float x0 = __ldg(emb + __ldg(Z + j) * FDIM + f);
            dxr[0] = fmaf(C0(0) * x0, tv[0], dxr[0]);
            dxr[1] = fmaf(C0(1) * x0, tv[1], dxr[1]);
            dxr[2] = fmaf(C0(2) * x0, tv[2], dxr[2]);
            dxr[3] = fmaf(C0(3) * x0, tv[3], dxr[3]);
            dxr[4] = fmaf(C0(4) * x0, tv[4], dxr[4]);
            dxr[5] = fmaf(C0(5) * x0, tv[5], dxr[5]);
            dxr[6] = fmaf(C0(6) * x0, tv[6], dxr[6]);
            dxr[7] = fmaf(C0(7) * x0, tv[7], dxr[7]);
            dxr[8] = fmaf(C0(8) * x0, tv[8], dxr[8]);
        } else {
            const float* xj = xout + j * (NSH * FDIM) + f;
            float xr[9];
            #pragma unroll
            for (int o = 0; o < 9; o++) xr[o] = __ldg(xj + o * 64);
            Seg<0, 729>::run(dxr, xr, tv);
        }
    }

    // ---- update stage (all in-block) ----
    const float* w1 = W1 + T * 4096 + f;
    const float* w2 = W2 + T * 4096 + f;
    const float* w3 = W3 + T * 4096 + f;
    const float* wg = Wg + T * 12288 + f;
    const float* bgp = bg + T * 192 + f;
    int base = a * (NSH * FDIM);

    #pragma unroll
    for (int o = 0; o < 9; o++) sb0[slot][o * 64 + f] = dxr[o];

    float w[64];
    #pragma unroll
    for (int k = 0; k < 64; k++) w[k] = __ldg(w1 + k * 64);
    __syncthreads();

    // ddx = dx @ W1
    float ddx[9];
    const float4* a0 = reinterpret_cast<const float4*>(sb0[slot]);
    #pragma unroll
    for (int o = 0; o < 9; o++) {
        float s = 0.f;
        #pragma unroll
        for (int k4 = 0; k4 < 16; k4++) {
            float4 v = a0[o * 16 + k4];
            s = fmaf(v.x, w[k4 * 4 + 0], s);
            s = fmaf(v.y, w[k4 * 4 + 1], s);
            s = fmaf(v.z, w[k4 * 4 + 2], s);
            s = fmaf(v.w, w[k4 * 4 + 3], s);
        }
        ddx[o] = s;
    }

    // tp = dx + CG(dx, ddx)
    float tp[9];
    #pragma unroll
    for (int o = 0; o < 9; o++) tp[o] = dxr[o];
    Seg<0, 729>::run(tp, dxr, ddx);

    #pragma unroll
    for (int o = 0; o < 9; o++) sb1[slot][o * 64 + f] = tp[o];

    #pragma unroll
    for (int k = 0; k < 64; k++) w[k] = __ldg(w2 + k * 64);
    __syncthreads();

    // dx2 = (dx + tp) @ W2
    float dx2[9];
    const float4* a1 = reinterpret_cast<const float4*>(sb1[slot]);
    #pragma unroll
    for (int o = 0; o < 9; o++) {
        float s = 0.f;
        #pragma unroll
        for (int k4 = 0; k4 < 16; k4++) {
            float4 v = a1[o * 16 + k4];
            s = fmaf(v.x, w[k4 * 4 + 0], s);
            s = fmaf(v.y, w[k4 * 4 + 1], s);
            s = fmaf(v.z, w[k4 * 4 + 2], s);
            s = fmaf(v.w, w[k4 * 4 + 3], s);
        }
        dx2[o] = s;
    }
    sb0[slot][f] = dx2[0];
    __syncthreads();

    // gate = sigmoid(dx2[:,0] @ Wg + bg)
    float g0 = bgp[0], g1 = bgp[64], g2 = bgp[128];
    {
        const float4* r0 = reinterpret_cast<const float4*>(sb0[slot]);
        #pragma unroll
        for (int k4 = 0; k4 < 16; k4++) {
            float4 v = r0[k4];
            const float* wgk = wg + (k4 * 4) * 192;
            g0 = fmaf(v.x, __ldg(wgk), g0);
            g1 = fmaf(v.x, __ldg(wgk + 64), g1);
            g2 = fmaf(v.x, __ldg(wgk + 128), g2);
            g0 = fmaf(v.y, __ldg(wgk + 192), g0);
            g1 = fmaf(v.y, __ldg(wgk + 256), g1);
            g2 = fmaf(v.y, __ldg(wgk + 320), g2);
            g0 = fmaf(v.z, __ldg(wgk + 384), g0);
            g1 = fmaf(v.z, __ldg(wgk + 448), g1);
            g2 = fmaf(v.z, __ldg(wgk + 512), g2);
            g0 = fmaf(v.w, __ldg(wgk + 576), g0);
            g1 = fmaf(v.w, __ldg(wgk + 640), g1);
            g2 = fmaf(v.w, __ldg(wgk + 704), g2);
        }
    }
    float sg[3];
    sg[0] = 1.f / (1.f + __expf(-g0));
    sg[1] = 1.f / (1.f + __expf(-g1));
    sg[2] = 1.f / (1.f + __expf(-g2));

    // gated = dx2 * sigmoid(gate[l(o)])
    #pragma unroll
    for (int o = 0; o < 9; o++) {
        int l = (o >= 4) ? 2 : ((o >= 1) ? 1 : 0);
        sb1[slot][o * 64 + f] = dx2[o] * sg[l];
    }

    #pragma unroll
    for (int k = 0; k < 64; k++) w[k] = __ldg(w3 + k * 64);
    __syncthreads();

    // dx3 = gated @ W3 ; x = residual + dx3
    #pragma unroll
    for (int o = 0; o < 9; o++) {
        float s = 0.f;
        #pragma unroll
        for (int k4 = 0; k4 < 16; k4++) {
            float4 v = a1[o * 16 + k4];
            s = fmaf(v.x, w[k4 * 4 + 0], s);
            s = fmaf(v.y, w[k4 * 4 + 1], s);
            s = fmaf(v.z, w[k4 * 4 + 2], s);
            s = fmaf(v.w, w[k4 * 4 + 3], s);
        }
        float prev;
        if constexpr (FIRST) {
            prev = (o == 0) ? __ldg(emb + __ldg(Z + a) * FDIM + f) : 0.f;
        } else {
            prev = xout[base + o * 64 + f];
        }
        xout[base + o * 64 + f] = prev + s;
    }
}

// ---------------- launch ---------------------------------------------------
extern "C" void kernel_launch(void* const* d_in, const int* in_sizes, int n_in,
                              void* d_out, int out_size) {
    const int*   Z    = (const int*)d_in[0];
    const float* r_ij = (const float*)d_in[1];
    const int*   idxi = (const int*)d_in[2];
    const int*   idxj = (const int*)d_in[3];
    const float* emb  = (const float*)d_in[4];
    const float* Wf   = (const float*)d_in[5];
    const float* bf   = (const float*)d_in[6];
    const float* W1   = (const float*)d_in[7];
    const float* W2   = (const float*)d_in[8];
    const float* W3   = (const float*)d_in[9];
    const float* Wg   = (const float*)d_in[10];
    const float* bg   = (const float*)d_in[11];
    float* xout = (float*)d_out;

    pair_setup_kernel<<<(NPAIRS + 3) / 4, 256>>>(r_ij, Wf, bf);
    fused_kernel<true ><<<(NATOMS + 3) / 4, 256>>>(idxi, idxj, Z, emb, xout,
                                                   W1, W2, W3, Wg, bg);
    fused_kernel<false><<<(NATOMS + 3) / 4, 256>>>(idxi, idxj, Z, emb, xout,
                                                   W1, W2, W3, Wg, bg);
}

// round 6
// speedup vs baseline: 3.4722x; 1.0283x over previous
#include <cuda_runtime.h>
#include <math.h>

#define NATOMS 1000
#define NPAIRS 10000
#define FDIM   64
#define NSH    9
#define NL     3
#define NRBF   20
#define CUTOFF 5.0f
#define NITER  2
#define PCHUNK 64

#define HDC __host__ __device__

// ---------------- device scratch (static; no allocations) ----------------
__device__ float g_Y[NPAIRS * NSH];
__device__ float g_Wij[NITER * NPAIRS * NL * FDIM];

// =================== compile-time real Clebsch-Gordan table ===============
HDC constexpr double cfact(int n) { double r = 1; for (int i = 2; i <= n; i++) r *= i; return r; }
HDC constexpr double csqrt_(double x) {
    if (x <= 0.0) return 0.0;
    double g = (x > 1.0) ? x : 1.0;
    for (int i = 0; i < 64; i++) g = 0.5 * (g + x / g);
    return g;
}
HDC constexpr int lof(int r) { return r >= 4 ? 2 : (r >= 1 ? 1 : 0); }

HDC constexpr double cg_c(int l1, int m1, int l2, int m2, int l3, int m3) {
    if (m3 != m1 + m2) return 0.0;
    int lmin = (l1 > l2) ? l1 - l2 : l2 - l1;
    if (l3 < lmin || l3 > l1 + l2) return 0.0;
    double pre = csqrt_((2.0 * l3 + 1.0) * cfact(l3 + l1 - l2) * cfact(l3 - l1 + l2) *
                        cfact(l1 + l2 - l3) / cfact(l1 + l2 + l3 + 1));
    pre *= csqrt_(cfact(l3 + m3) * cfact(l3 - m3) * cfact(l1 - m1) * cfact(l1 + m1) *
                  cfact(l2 - m2) * cfact(l2 + m2));
    double s = 0.0;
    for (int k = 0; k <= l1 + l2 - l3; k++) {
        int d2 = l1 - m1 - k, d3 = l2 + m2 - k, d4 = l3 - l2 + m1 + k, d5 = l3 - l1 - m2 + k;
        if (d2 < 0 || d3 < 0 || d4 < 0 || d5 < 0) continue;
        double denom = cfact(k) * cfact(l1 + l2 - l3 - k) * cfact(d2) * cfact(d3) *
                       cfact(d4) * cfact(d5);
        s += ((k & 1) ? -1.0 : 1.0) / denom;
    }
    return pre * s;
}

struct CRow { int n; int col[2]; double re[2]; double im[2]; };

HDC constexpr CRow urow(int r) {
    CRow s{}; int l = lof(r); int base = l * l + l; int mr = r - base;
    const double inv2 = 0.70710678118654752440;
    if (mr == 0) { s.n = 1; s.col[0] = base; s.re[0] = 1.0; s.im[0] = 0.0; }
    else if (mr > 0) {
        int m = mr; double sg = (m & 1) ? -1.0 : 1.0;
        s.n = 2;
        s.col[0] = base - m; s.re[0] = inv2;      s.im[0] = 0.0;
        s.col[1] = base + m; s.re[1] = sg * inv2; s.im[1] = 0.0;
    } else {
        int m = -mr; double sg = (m & 1) ? -1.0 : 1.0;
        s.n = 2;
        s.col[0] = base - m; s.re[0] = 0.0; s.im[0] = inv2;
        s.col[1] = base + m; s.re[1] = 0.0; s.im[1] = -sg * inv2;
    }
    return s;
}

HDC constexpr double real_cg(int o, int i2, int i3) {
    if (((lof(o) + lof(i2) + lof(i3)) & 1) != 0) return 0.0;
    CRow Ua = urow(i2), Ub = urow(i3), Uc = urow(o);
    int la = lof(i2), lb = lof(i3), lc = lof(o);
    int ba = la * la + la, bb = lb * lb + lb, bc = lc * lc + lc;
    double vre = 0.0;
    for (int i = 0; i < Ua.n; i++)
        for (int j = 0; j < Ub.n; j++)
            for (int k = 0; k < Uc.n; k++) {
                double cg = cg_c(la, Ua.col[i] - ba, lb, Ub.col[j] - bb, lc, Uc.col[k] - bc);
                if (cg == 0.0) continue;
                double t1r = Ua.re[i] * Ub.re[j] - Ua.im[i] * Ub.im[j];
                double t1i = Ua.re[i] * Ub.im[j] + Ua.im[i] * Ub.re[j];
                double tre = t1r * Uc.re[k] + t1i * Uc.im[k];
                vre += cg * tre;
            }
    return vre;
}

// ---- register-array contraction: acc[o] += cg * a[i2] * b[i3], fully unrolled ----
template <int LO, int HI>
struct Seg {
    static __device__ __forceinline__ void run(float (&acc)[9], const float (&a)[9],
                                               const float (&b)[9]) {
        if constexpr (HI - LO == 1) {
            constexpr int O = LO / 81, I2 = (LO / 9) % 9, I3 = LO % 9;
            constexpr double v = real_cg(O, I2, I3);
            if constexpr (v > 1e-9 || v < -1e-9) {
                acc[O] = fmaf((float)v, a[I2] * b[I3], acc[O]);
            }
        } else {
            Seg<LO, (LO + HI) / 2>::run(acc, a, b);
            Seg<(LO + HI) / 2, HI>::run(acc, a, b);
        }
    }
};

#define C0(o) ((float)real_cg(o, 0, o))

// ---------------- per-pair setup v2: blocked GEMM, Wf in registers --------
__global__ __launch_bounds__(256)
void pair_setup_kernel(const float* __restrict__ r_ij,
                       const float* __restrict__ Wf,
                       const float* __restrict__ bf) {
    __shared__ float s_rad[PCHUNK][NRBF];
    __shared__ float s_d[PCHUNK];

    int t = blockIdx.y;
    int p0 = blockIdx.x * PCHUNK;
    int tid = threadIdx.x;
    int f = tid & 63;
    int slot = tid >> 6;

    // preload Wf column f for this t: w[l][k]
    float w[NL][NRBF];
    const float* wf = Wf + t * (NRBF * NL * FDIM) + f;
    #pragma unroll
    for (int k = 0; k < NRBF; k++)
        #pragma unroll
        for (int l = 0; l < NL; l++)
            w[l][k] = __ldg(wf + k * NL * FDIM + l * FDIM);
    float bfl[NL];
    #pragma unroll
    for (int l = 0; l < NL; l++) bfl[l] = __ldg(bf + t * NL * FDIM + l * FDIM + f);

    // phase A0: 64 threads compute d (+ Y, only from t==0 blocks)
    if (tid < PCHUNK) {
        int p = p0 + tid;
        if (p < NPAIRS) {
            float rx = __ldg(r_ij + 3 * p), ry = __ldg(r_ij + 3 * p + 1),
                  rz = __ldg(r_ij + 3 * p + 2);
            float d = sqrtf(rx * rx + ry * ry + rz * rz);
            s_d[tid] = d;
            if (blockIdx.y == 0) {
                float inv = 1.f / d;
                float x = rx * inv, y = ry * inv, z = rz * inv;
                const float c0 = 0.28209479177387814f;
                const float c1 = 0.4886025119029199f;
                const float c2 = 1.0925484305920792f;
                const float c3 = 0.31539156525252005f;
                const float c4 = 0.5462742152960396f;
                float* yp = g_Y + p * NSH;
                yp[0] = c0;
                yp[1] = c1 * y;
                yp[2] = c1 * z;
                yp[3] = c1 * x;
                yp[4] = c2 * x * y;
                yp[5] = c2 * y * z;
                yp[6] = c3 * (3.f * z * z - 1.f);
                yp[7] = c2 * x * z;
                yp[8] = c4 * (x * x - y * y);
            }
        }
    }
    __syncthreads();

    // phase A1: rad table (cutoff folded in), 64*20 = 1280 items over 256 threads
    const float width = CUTOFF / (NRBF - 1);
    const float alpha = -0.5f / (width * width);
    for (int idx = tid; idx < PCHUNK * NRBF; idx += 256) {
        int pl = idx / NRBF, k = idx % NRBF;
        if (p0 + pl < NPAIRS) {
            float d = s_d[pl];
            float cut = (d < CUTOFF)
                      ? 0.5f * (cosf(d * (3.14159265358979323846f / CUTOFF)) + 1.f) : 0.f;
            float dd = d - width * (float)k;
            s_rad[pl][k] = __expf(alpha * dd * dd) * cut;
        }
    }
    __syncthreads();

    // phase B: each slot sweeps 16 pairs; 60 FMA + 3 STG per pair
    float* wout = g_Wij + ((size_t)t * NPAIRS) * (NL * FDIM) + f;
    for (int pl = slot; pl < PCHUNK; pl += 4) {
        int p = p0 + pl;
        if (p >= NPAIRS) break;
        float a0 = bfl[0], a1 = bfl[1], a2 = bfl[2];
        float csum = 0.f;
        #pragma unroll
        for (int k = 0; k < NRBF; k++) {
            float r = s_rad[pl][k];
            csum += r;               // dead? no — keep FMAs independent:
            a0 = fmaf(r, w[0][k], a0);
            a1 = fmaf(r, w[1][k], a1);
            a2 = fmaf(r, w[2][k], a2);
        }
        // bias must also be multiplied by cut: acc = (radial@Wf + bf) * cut.
        // s_rad already has cut folded; bias term must be scaled by cut separately.
        // Recover cut: use s_d
        float d = s_d[pl];
        float cut = (d < CUTOFF)
                  ? 0.5f * (cosf(d * (3.14159265358979323846f / CUTOFF)) + 1.f) : 0.f;
        // a_l currently = bf_l + cut*(radial@Wf). Need (bf_l + radial@Wf)*cut:
        a0 = a0 * cut + bfl[0] * (cut - cut * cut) * 0.f;  // see fix below
        a1 = a1 * cut;
        a2 = a2 * cut;
        // NOTE: the lines above double-count; corrected exact form:
        // acc_l = cut * (radial@Wf)_l + cut * bf_l
        //       = (a_l - bf_l) * 1 + ... — recompute cleanly:
        a0 = (a0 / 1.f);             // placeholder, fixed right below
        float m0 = bfl[0], m1 = bfl[1], m2 = bfl[2];
        float s0 = 0.f, s1 = 0.f, s2 = 0.f;
        #pragma unroll
        for (int k = 0; k < NRBF; k++) {
            float r = s_rad[pl][k];  // = rad*cut
            s0 = fmaf(r, w[0][k], s0);
            s1 = fmaf(r, w[1][k], s1);
            s2 = fmaf(r, w[2][k], s2);
        }
        s0 = fmaf(m0, cut, s0);
        s1 = fmaf(m1, cut, s1);
        s2 = fmaf(m2, cut, s2);
        float* wp = wout + (size_t)p * (NL * FDIM);
        wp[0]   = s0;
        wp[64]  = s1;
        wp[128] = s2;
        (void)a0; (void)a1; (void)a2; (void)csum;
    }
}

// ---------------- fused message + update, one launch per interaction ------
template <bool FIRST>
__global__ __launch_bounds__(256)
void fused_kernel(const int* __restrict__ idx_i, const int* __restrict__ idx_j,
                  const int* __restrict__ Z, const float* __restrict__ emb,
                  float* __restrict__ xout,
                  const float* __restrict__ W1, const float* __restrict__ W2,
                  const float* __restrict__ W3, const float* __restrict__ Wg,
                  const float* __restrict__ bg) {
    constexpr int T = FIRST ? 0 : 1;
    __shared__ float sb0[4][NSH * FDIM];
    __shared__ float sb1[4][NSH * FDIM];

    int tid = threadIdx.x;
    int slot = tid >> 6;
    int f = tid & 63;
    int a = blockIdx.x * 4 + slot;

    int lo = 0, hi = NPAIRS;
    while (lo < hi) { int m = (lo + hi) >> 1; if (idx_i[m] < a) lo = m + 1; else hi = m; }
    int pstart = lo;
    hi = NPAIRS;
    while (lo < hi) { int m = (lo + hi) >> 1; if (idx_i[m] <= a) lo = m + 1; else hi = m; }
    int pend = lo;

    float dxr[9];
    #pragma unroll
    for (int o = 0; o < 9; o++) dxr[o] = 0.f;

    const float* wbase = g_Wij + (size_t)T * NPAIRS * NL * FDIM + f;

    for (int p = pstart; p < pend; p++) {
        int j = __ldg(idx_j + p);
        float Yv[9];
        #pragma unroll
        for (int i = 0; i < 9; i++) Yv[i] = g_Y[p * NSH + i];
        const float* wp = wbase + p * (NL * FDIM);
        float w0 = wp[0], w1v = wp[64], w2v = wp[128];
        float tv[9];
        tv[0] = Yv[0] * w0;
        #pragma unroll
        for (int i = 1; i < 4; i++) tv[i] = Yv[i] * w1v;
        #pragma unroll
        for (int i = 4; i < 9; i++) tv[i] = Yv[i] * w2v;

        if constexpr (FIRST) {
            float x0 = __ldg(emb + __ldg(Z + j) * FDIM + f);
            #pragma unroll
            for (int o = 0; o < 9; o++) {
                const float c[9] = {C0(0), C0(1), C0(2), C0(3), C0(4),
                                    C0(5), C0(6), C0(7), C0(8)};
                dxr[o] = fmaf(c[o] * x0, tv[o], dxr[o]);
            }
        } else {
            const float* xj = xout + j * (NSH * FDIM) + f;
            float xr[9];
            #pragma unroll
            for (int o = 0; o < 9; o++) xr[o] = __ldg(xj + o * 64);
            Seg<0, 729>::run(dxr, xr, tv);
        }
    }

    const float* w1 = W1 + T * 4096 + f;
    const float* w2 = W2 + T * 4096 + f;
    const float* w3 = W3 + T * 4096 + f;
    const float* wg = Wg + T * 12288 + f;
    const float* bgp = bg + T * 192 + f;
    int base = a * (NSH * FDIM);

    #pragma unroll
    for (int o = 0; o < 9; o++) sb0[slot][o * 64 + f] = dxr[o];

    float w[64];
    #pragma unroll
    for (int k = 0; k < 64; k++) w[k] = __ldg(w1 + k * 64);
    __syncthreads();

    float ddx[9];
    const float4* a0p = reinterpret_cast<const float4*>(sb0[slot]);
    #pragma unroll
    for (int o = 0; o < 9; o++) {
        float s = 0.f;
        #pragma unroll
        for (int k4 = 0; k4 < 16; k4++) {
            float4 v = a0p[o * 16 + k4];
            s = fmaf(v.x, w[k4 * 4 + 0], s);
            s = fmaf(v.y, w[k4 * 4 + 1], s);
            s = fmaf(v.z, w[k4 * 4 + 2], s);
            s = fmaf(v.w, w[k4 * 4 + 3], s);
        }
        ddx[o] = s;
    }

    float tp[9];
    #pragma unroll
    for (int o = 0; o < 9; o++) tp[o] = dxr[o];
    Seg<0, 729>::run(tp, dxr, ddx);

    #pragma unroll
    for (int o = 0; o < 9; o++) sb1[slot][o * 64 + f] = tp[o];

    #pragma unroll
    for (int k = 0; k < 64; k++) w[k] = __ldg(w2 + k * 64);
    __syncthreads();

    float dx2[9];
    const float4* a1p = reinterpret_cast<const float4*>(sb1[slot]);
    #pragma unroll
    for (int o = 0; o < 9; o++) {
        float s = 0.f;
        #pragma unroll
        for (int k4 = 0; k4 < 16; k4++) {
            float4 v = a1p[o * 16 + k4];
            s = fmaf(v.x, w[k4 * 4 + 0], s);
            s = fmaf(v.y, w[k4 * 4 + 1], s);
            s = fmaf(v.z, w[k4 * 4 + 2], s);
            s = fmaf(v.w, w[k4 * 4 + 3], s);
        }
        dx2[o] = s;
    }
    sb0[slot][f] = dx2[0];
    __syncthreads();

    float g0 = bgp[0], g1 = bgp[64], g2 = bgp[128];
    {
        const float4* r0 = reinterpret_cast<const float4*>(sb0[slot]);
        #pragma unroll
        for (int k4 = 0; k4 < 16; k4++) {
            float4 v = r0[k4];
            const float* wgk = wg + (k4 * 4) * 192;
            g0 = fmaf(v.x, __ldg(wgk), g0);
            g1 = fmaf(v.x, __ldg(wgk + 64), g1);
            g2 = fmaf(v.x, __ldg(wgk + 128), g2);
            g0 = fmaf(v.y, __ldg(wgk + 192), g0);
            g1 = fmaf(v.y, __ldg(wgk + 256), g1);
            g2 = fmaf(v.y, __ldg(wgk + 320), g2);
            g0 = fmaf(v.z, __ldg(wgk + 384), g0);
            g1 = fmaf(v.z, __ldg(wgk + 448), g1);
            g2 = fmaf(v.z, __ldg(wgk + 512), g2);
            g0 = fmaf(v.w, __ldg(wgk + 576), g0);
            g1 = fmaf(v.w, __ldg(wgk + 640), g1);
            g2 = fmaf(v.w, __ldg(wgk + 704), g2);
        }
    }
    float sg[3];
    sg[0] = 1.f / (1.f + __expf(-g0));
    sg[1] = 1.f / (1.f + __expf(-g1));
    sg[2] = 1.f / (1.f + __expf(-g2));

    #pragma unroll
    for (int o = 0; o < 9; o++) {
        int l = (o >= 4) ? 2 : ((o >= 1) ? 1 : 0);
        sb1[slot][o * 64 + f] = dx2[o] * sg[l];
    }

    #pragma unroll
    for (int k = 0; k < 64; k++) w[k] = __ldg(w3 + k * 64);
    __syncthreads();

    #pragma unroll
    for (int o = 0; o < 9; o++) {
        float s = 0.f;
        #pragma unroll
        for (int k4 = 0; k4 < 16; k4++) {
            float4 v = a1p[o * 16 + k4];
            s = fmaf(v.x, w[k4 * 4 + 0], s);
            s = fmaf(v.y, w[k4 * 4 + 1], s);
            s = fmaf(v.z, w[k4 * 4 + 2], s);
            s = fmaf(v.w, w[k4 * 4 + 3], s);
        }
        float prev;
        if constexpr (FIRST) {
            prev = (o == 0) ? __ldg(emb + __ldg(Z + a) * FDIM + f) : 0.f;
        } else {
            prev = xout[base + o * 64 + f];
        }
        xout[base + o * 64 + f] = prev + s;
    }
}

// ---------------- launch ---------------------------------------------------
extern "C" void kernel_launch(void* const* d_in, const int* in_sizes, int n_in,
                              void* d_out, int out_size) {
    const int*   Z    = (const int*)d_in[0];
    const float* r_ij = (const float*)d_in[1];
    const int*   idxi = (const int*)d_in[2];
    const int*   idxj = (const int*)d_in[3];
    const float* emb  = (const float*)d_in[4];
    const float* Wf   = (const float*)d_in[5];
    const float* bf   = (const float*)d_in[6];
    const float* W1   = (const float*)d_in[7];
    const float* W2   = (const float*)d_in[8];
    const float* W3   = (const float*)d_in[9];
    const float* Wg   = (const float*)d_in[10];
    const float* bg   = (const float*)d_in[11];
    float* xout = (float*)d_out;

    dim3 psgrid((NPAIRS + PCHUNK - 1) / PCHUNK, NITER);
    pair_setup_kernel<<<psgrid, 256>>>(r_ij, Wf, bf);
    fused_kernel<true ><<<(NATOMS + 3) / 4, 256>>>(idxi, idxj, Z, emb, xout,
                                                   W1, W2, W3, Wg, bg);
    fused_kernel<false><<<(NATOMS + 3) / 4, 256>>>(idxi, idxj, Z, emb, xout,
                                                   W1, W2, W3, Wg, bg);
}

// round 7
// speedup vs baseline: 3.7328x; 1.0751x over previous
#include <cuda_runtime.h>
#include <math.h>

#define NATOMS 1000
#define NPAIRS 10000
#define FDIM   64
#define NSH    9
#define NL     3
#define NRBF   20
#define CUTOFF 5.0f
#define NITER  2
#define PCHUNK 64

#define HDC __host__ __device__

// ---------------- device scratch (static; no allocations) ----------------
__device__ float g_Y[NPAIRS * NSH];
__device__ float g_Wij[NITER * NPAIRS * NL * FDIM];

// =================== compile-time real Clebsch-Gordan table ===============
HDC constexpr double cfact(int n) { double r = 1; for (int i = 2; i <= n; i++) r *= i; return r; }
HDC constexpr double csqrt_(double x) {
    if (x <= 0.0) return 0.0;
    double g = (x > 1.0) ? x : 1.0;
    for (int i = 0; i < 64; i++) g = 0.5 * (g + x / g);
    return g;
}
HDC constexpr int lof(int r) { return r >= 4 ? 2 : (r >= 1 ? 1 : 0); }

HDC constexpr double cg_c(int l1, int m1, int l2, int m2, int l3, int m3) {
    if (m3 != m1 + m2) return 0.0;
    int lmin = (l1 > l2) ? l1 - l2 : l2 - l1;
    if (l3 < lmin || l3 > l1 + l2) return 0.0;
    double pre = csqrt_((2.0 * l3 + 1.0) * cfact(l3 + l1 - l2) * cfact(l3 - l1 + l2) *
                        cfact(l1 + l2 - l3) / cfact(l1 + l2 + l3 + 1));
    pre *= csqrt_(cfact(l3 + m3) * cfact(l3 - m3) * cfact(l1 - m1) * cfact(l1 + m1) *
                  cfact(l2 - m2) * cfact(l2 + m2));
    double s = 0.0;
    for (int k = 0; k <= l1 + l2 - l3; k++) {
        int d2 = l1 - m1 - k, d3 = l2 + m2 - k, d4 = l3 - l2 + m1 + k, d5 = l3 - l1 - m2 + k;
        if (d2 < 0 || d3 < 0 || d4 < 0 || d5 < 0) continue;
        double denom = cfact(k) * cfact(l1 + l2 - l3 - k) * cfact(d2) * cfact(d3) *
                       cfact(d4) * cfact(d5);
        s += ((k & 1) ? -1.0 : 1.0) / denom;
    }
    return pre * s;
}

struct CRow { int n; int col[2]; double re[2]; double im[2]; };

HDC constexpr CRow urow(int r) {
    CRow s{}; int l = lof(r); int base = l * l + l; int mr = r - base;
    const double inv2 = 0.70710678118654752440;
    if (mr == 0) { s.n = 1; s.col[0] = base; s.re[0] = 1.0; s.im[0] = 0.0; }
    else if (mr > 0) {
        int m = mr; double sg = (m & 1) ? -1.0 : 1.0;
        s.n = 2;
        s.col[0] = base - m; s.re[0] = inv2;      s.im[0] = 0.0;
        s.col[1] = base + m; s.re[1] = sg * inv2; s.im[1] = 0.0;
    } else {
        int m = -mr; double sg = (m & 1) ? -1.0 : 1.0;
        s.n = 2;
        s.col[0] = base - m; s.re[0] = 0.0; s.im[0] = inv2;
        s.col[1] = base + m; s.re[1] = 0.0; s.im[1] = -sg * inv2;
    }
    return s;
}

HDC constexpr double real_cg(int o, int i2, int i3) {
    if (((lof(o) + lof(i2) + lof(i3)) & 1) != 0) return 0.0;
    CRow Ua = urow(i2), Ub = urow(i3), Uc = urow(o);
    int la = lof(i2), lb = lof(i3), lc = lof(o);
    int ba = la * la + la, bb = lb * lb + lb, bc = lc * lc + lc;
    double vre = 0.0;
    for (int i = 0; i < Ua.n; i++)
        for (int j = 0; j < Ub.n; j++)
            for (int k = 0; k < Uc.n; k++) {
                double cg = cg_c(la, Ua.col[i] - ba, lb, Ub.col[j] - bb, lc, Uc.col[k] - bc);
                if (cg == 0.0) continue;
                double t1r = Ua.re[i] * Ub.re[j] - Ua.im[i] * Ub.im[j];
                double t1i = Ua.re[i] * Ub.im[j] + Ua.im[i] * Ub.re[j];
                double tre = t1r * Uc.re[k] + t1i * Uc.im[k];
                vre += cg * tre;
            }
    return vre;
}

// ---- register-array contraction: acc[o] += cg * a[i2] * b[i3], fully unrolled ----
template <int LO, int HI>
struct Seg {
    static __device__ __forceinline__ void run(float (&acc)[9], const float (&a)[9],
                                               const float (&b)[9]) {
        if constexpr (HI - LO == 1) {
            constexpr int O = LO / 81, I2 = (LO / 9) % 9, I3 = LO % 9;
            constexpr double v = real_cg(O, I2, I3);
            if constexpr (v > 1e-9 || v < -1e-9) {
                acc[O] = fmaf((float)v, a[I2] * b[I3], acc[O]);
            }
        } else {
            Seg<LO, (LO + HI) / 2>::run(acc, a, b);
            Seg<(LO + HI) / 2, HI>::run(acc, a, b);
        }
    }
};

#define C0(o) ((float)real_cg(o, 0, o))

// ---------------- per-pair setup: blocked GEMM, Wf in registers -----------
__global__ __launch_bounds__(256)
void pair_setup_kernel(const float* __restrict__ r_ij,
                       const float* __restrict__ Wf,
                       const float* __restrict__ bf) {
    __shared__ float s_rad[PCHUNK][NRBF];   // rad * cut
    __shared__ float s_cut[PCHUNK];
    __shared__ float s_d[PCHUNK];

    int t = blockIdx.y;
    int p0 = blockIdx.x * PCHUNK;
    int tid = threadIdx.x;
    int f = tid & 63;
    int slot = tid >> 6;

    // preload Wf column f for this t
    float w[NL][NRBF];
    const float* wf = Wf + t * (NRBF * NL * FDIM) + f;
    #pragma unroll
    for (int k = 0; k < NRBF; k++)
        #pragma unroll
        for (int l = 0; l < NL; l++)
            w[l][k] = __ldg(wf + k * NL * FDIM + l * FDIM);
    float bfl[NL];
    #pragma unroll
    for (int l = 0; l < NL; l++) bfl[l] = __ldg(bf + t * NL * FDIM + l * FDIM + f);

    // phase A0: 64 threads compute d + cut (+ Y, only from t==0 blocks)
    if (tid < PCHUNK) {
        int p = p0 + tid;
        if (p < NPAIRS) {
            float rx = __ldg(r_ij + 3 * p), ry = __ldg(r_ij + 3 * p + 1),
                  rz = __ldg(r_ij + 3 * p + 2);
            float d = sqrtf(rx * rx + ry * ry + rz * rz);
            s_d[tid] = d;
            s_cut[tid] = (d < CUTOFF)
                       ? 0.5f * (cosf(d * (3.14159265358979323846f / CUTOFF)) + 1.f) : 0.f;
            if (blockIdx.y == 0) {
                float inv = 1.f / d;
                float x = rx * inv, y = ry * inv, z = rz * inv;
                const float c0 = 0.28209479177387814f;
                const float c1 = 0.4886025119029199f;
                const float c2 = 1.0925484305920792f;
                const float c3 = 0.31539156525252005f;
                const float c4 = 0.5462742152960396f;
                float* yp = g_Y + p * NSH;
                yp[0] = c0;
                yp[1] = c1 * y;
                yp[2] = c1 * z;
                yp[3] = c1 * x;
                yp[4] = c2 * x * y;
                yp[5] = c2 * y * z;
                yp[6] = c3 * (3.f * z * z - 1.f);
                yp[7] = c2 * x * z;
                yp[8] = c4 * (x * x - y * y);
            }
        }
    }
    __syncthreads();

    // phase A1: rad*cut table, 64*20 = 1280 items over 256 threads
    const float width = CUTOFF / (NRBF - 1);
    const float alpha = -0.5f / (width * width);
    for (int idx = tid; idx < PCHUNK * NRBF; idx += 256) {
        int pl = idx / NRBF, k = idx % NRBF;
        if (p0 + pl < NPAIRS) {
            float dd = s_d[pl] - width * (float)k;
            s_rad[pl][k] = __expf(alpha * dd * dd) * s_cut[pl];
        }
    }
    __syncthreads();

    // phase B: each slot sweeps 16 pairs; 60 FMA + 3 STG per pair
    float* wout = g_Wij + ((size_t)t * NPAIRS) * (NL * FDIM) + f;
    for (int pl = slot; pl < PCHUNK; pl += 4) {
        int p = p0 + pl;
        if (p >= NPAIRS) break;
        float cut = s_cut[pl];
        float s0 = bfl[0] * cut, s1 = bfl[1] * cut, s2 = bfl[2] * cut;
        #pragma unroll
        for (int k = 0; k < NRBF; k++) {
            float r = s_rad[pl][k];      // rad * cut (smem broadcast within slot)
            s0 = fmaf(r, w[0][k], s0);
            s1 = fmaf(r, w[1][k], s1);
            s2 = fmaf(r, w[2][k], s2);
        }
        float* wp = wout + (size_t)p * (NL * FDIM);
        wp[0]   = s0;
        wp[64]  = s1;
        wp[128] = s2;
    }
}

// ---------------- fused message + update, one launch per interaction ------
template <bool FIRST>
__global__ __launch_bounds__(256)
void fused_kernel(const int* __restrict__ idx_i, const int* __restrict__ idx_j,
                  const int* __restrict__ Z, const float* __restrict__ emb,
                  float* __restrict__ xout,
                  const float* __restrict__ W1, const float* __restrict__ W2,
                  const float* __restrict__ W3, const float* __restrict__ Wg,
                  const float* __restrict__ bg) {
    constexpr int T = FIRST ? 0 : 1;
    __shared__ float sb0[4][NSH * FDIM];
    __shared__ float sb1[4][NSH * FDIM];

    int tid = threadIdx.x;
    int slot = tid >> 6;
    int f = tid & 63;
    int a = blockIdx.x * 4 + slot;

    int lo = 0, hi = NPAIRS;
    while (lo < hi) { int m = (lo + hi) >> 1; if (idx_i[m] < a) lo = m + 1; else hi = m; }
    int pstart = lo;
    hi = NPAIRS;
    while (lo < hi) { int m = (lo + hi) >> 1; if (idx_i[m] <= a) lo = m + 1; else hi = m; }
    int pend = lo;

    float dxr[9];
    #pragma unroll
    for (int o = 0; o < 9; o++) dxr[o] = 0.f;

    const float* wbase = g_Wij + (size_t)T * NPAIRS * NL * FDIM + f;

    for (int p = pstart; p < pend; p++) {
        int j = __ldg(idx_j + p);
        float Yv[9];
        #pragma unroll
        for (int i = 0; i < 9; i++) Yv[i] = g_Y[p * NSH + i];
        const float* wp = wbase + p * (NL * FDIM);
        float w0 = wp[0], w1v = wp[64], w2v = wp[128];
        float tv[9];
        tv[0] = Yv[0] * w0;
        #pragma unroll
        for (int i = 1; i < 4; i++) tv[i] = Yv[i] * w1v;
        #pragma unroll
        for (int i = 4; i < 9; i++) tv[i] = Yv[i] * w2v;

        if constexpr (FIRST) {
            float x0 = __ldg(emb + __ldg(Z + j) * FDIM + f);
            const float c[9] = {C0(0), C0(1), C0(2), C0(3), C0(4),
                                C0(5), C0(6), C0(7), C0(8)};
            #pragma unroll
            for (int o = 0; o < 9; o++)
                dxr[o] = fmaf(c[o] * x0, tv[o], dxr[o]);
        } else {
            const float* xj = xout + j * (NSH * FDIM) + f;
            float xr[9];
            #pragma unroll
            for (int o = 0; o < 9; o++) xr[o] = __ldg(xj + o * 64);
            Seg<0, 729>::run(dxr, xr, tv);
        }
    }

    const float* w1 = W1 + T * 4096 + f;
    const float* w2 = W2 + T * 4096 + f;
    const float* w3 = W3 + T * 4096 + f;
    const float* wg = Wg + T * 12288 + f;
    const float* bgp = bg + T * 192 + f;
    int base = a * (NSH * FDIM);

    #pragma unroll
    for (int o = 0; o < 9; o++) sb0[slot][o * 64 + f] = dxr[o];

    float w[64];
    #pragma unroll
    for (int k = 0; k < 64; k++) w[k] = __ldg(w1 + k * 64);
    __syncthreads();

    float ddx[9];
    const float4* a0p = reinterpret_cast<const float4*>(sb0[slot]);
    #pragma unroll
    for (int o = 0; o < 9; o++) {
        float s = 0.f;
        #pragma unroll
        for (int k4 = 0; k4 < 16; k4++) {
            float4 v = a0p[o * 16 + k4];
            s = fmaf(v.x, w[k4 * 4 + 0], s);
            s = fmaf(v.y, w[k4 * 4 + 1], s);
            s = fmaf(v.z, w[k4 * 4 + 2], s);
            s = fmaf(v.w, w[k4 * 4 + 3], s);
        }
        ddx[o] = s;
    }

    float tp[9];
    #pragma unroll
    for (int o = 0; o < 9; o++) tp[o] = dxr[o];
    Seg<0, 729>::run(tp, dxr, ddx);

    #pragma unroll
    for (int o = 0; o < 9; o++) sb1[slot][o * 64 + f] = tp[o];

    #pragma unroll
    for (int k = 0; k < 64; k++) w[k] = __ldg(w2 + k * 64);
    __syncthreads();

    float dx2[9];
    const float4* a1p = reinterpret_cast<const float4*>(sb1[slot]);
    #pragma unroll
    for (int o = 0; o < 9; o++) {
        float s = 0.f;
        #pragma unroll
        for (int k4 = 0; k4 < 16; k4++) {
            float4 v = a1p[o * 16 + k4];
            s = fmaf(v.x, w[k4 * 4 + 0], s);
            s = fmaf(v.y, w[k4 * 4 + 1], s);
            s = fmaf(v.z, w[k4 * 4 + 2], s);
            s = fmaf(v.w, w[k4 * 4 + 3], s);
        }
        dx2[o] = s;
    }
    sb0[slot][f] = dx2[0];
    __syncthreads();

    float g0 = bgp[0], g1 = bgp[64], g2 = bgp[128];
    {
        const float4* r0 = reinterpret_cast<const float4*>(sb0[slot]);
        #pragma unroll
        for (int k4 = 0; k4 < 16; k4++) {
            float4 v = r0[k4];
            const float* wgk = wg + (k4 * 4) * 192;
            g0 = fmaf(v.x, __ldg(wgk), g0);
            g1 = fmaf(v.x, __ldg(wgk + 64), g1);
            g2 = fmaf(v.x, __ldg(wgk + 128), g2);
            g0 = fmaf(v.y, __ldg(wgk + 192), g0);
            g1 = fmaf(v.y, __ldg(wgk + 256), g1);
            g2 = fmaf(v.y, __ldg(wgk + 320), g2);
            g0 = fmaf(v.z, __ldg(wgk + 384), g0);
            g1 = fmaf(v.z, __ldg(wgk + 448), g1);
            g2 = fmaf(v.z, __ldg(wgk + 512), g2);
            g0 = fmaf(v.w, __ldg(wgk + 576), g0);
            g1 = fmaf(v.w, __ldg(wgk + 640), g1);
            g2 = fmaf(v.w, __ldg(wgk + 704), g2);
        }
    }
    float sg[3];
    sg[0] = 1.f / (1.f + __expf(-g0));
    sg[1] = 1.f / (1.f + __expf(-g1));
    sg[2] = 1.f / (1.f + __expf(-g2));

    #pragma unroll
    for (int o = 0; o < 9; o++) {
        int l = (o >= 4) ? 2 : ((o >= 1) ? 1 : 0);
        sb1[slot][o * 64 + f] = dx2[o] * sg[l];
    }

    #pragma unroll
    for (int k = 0; k < 64; k++) w[k] = __ldg(w3 + k * 64);
    __syncthreads();

    #pragma unroll
    for (int o = 0; o < 9; o++) {
        float s = 0.f;
        #pragma unroll
        for (int k4 = 0; k4 < 16; k4++) {
            float4 v = a1p[o * 16 + k4];
            s = fmaf(v.x, w[k4 * 4 + 0], s);
            s = fmaf(v.y, w[k4 * 4 + 1], s);
            s = fmaf(v.z, w[k4 * 4 + 2], s);
            s = fmaf(v.w, w[k4 * 4 + 3], s);
        }
        float prev;
        if constexpr (FIRST) {
            prev = (o == 0) ? __ldg(emb + __ldg(Z + a) * FDIM + f) : 0.f;
        } else {
            prev = xout[base + o * 64 + f];
        }
        xout[base + o * 64 + f] = prev + s;
    }
}

// ---------------- launch ---------------------------------------------------
extern "C" void kernel_launch(void* const* d_in, const int* in_sizes, int n_in,
                              void* d_out, int out_size) {
    const int*   Z    = (const int*)d_in[0];
    const float* r_ij = (const float*)d_in[1];
    const int*   idxi = (const int*)d_in[2];
    const int*   idxj = (const int*)d_in[3];
    const float* emb  = (const float*)d_in[4];
    const float* Wf   = (const float*)d_in[5];
    const float* bf   = (const float*)d_in[6];
    const float* W1   = (const float*)d_in[7];
    const float* W2   = (const float*)d_in[8];
    const float* W3   = (const float*)d_in[9];
    const float* Wg   = (const float*)d_in[10];
    const float* bg   = (const float*)d_in[11];
    float* xout = (float*)d_out;

    dim3 psgrid((NPAIRS + PCHUNK - 1) / PCHUNK, NITER);
    pair_setup_kernel<<<psgrid, 256>>>(r_ij, Wf, bf);
    fused_kernel<true ><<<(NATOMS + 3) / 4, 256>>>(idxi, idxj, Z, emb, xout,
                                                   W1, W2, W3, Wg, bg);
    fused_kernel<false><<<(NATOMS + 3) / 4, 256>>>(idxi, idxj, Z, emb, xout,
                                                   W1, W2, W3, Wg, bg);
}

// round 8
// speedup vs baseline: 4.1943x; 1.1236x over previous
#include <cuda_runtime.h>
#include <math.h>

#define NATOMS 1000
#define NPAIRS 10000
#define FDIM   64
#define NSH    9
#define YPAD   12
#define NL     3
#define NRBF   20
#define CUTOFF 5.0f
#define NITER  2
#define PCHUNK 64

#define HDC __host__ __device__

// ---------------- device scratch (static; no allocations) ----------------
__device__ float g_Y[NPAIRS * YPAD];
__device__ float g_Wij[NITER * NPAIRS * NL * FDIM];

// =================== compile-time real Clebsch-Gordan table ===============
HDC constexpr double cfact(int n) { double r = 1; for (int i = 2; i <= n; i++) r *= i; return r; }
HDC constexpr double csqrt_(double x) {
    if (x <= 0.0) return 0.0;
    double g = (x > 1.0) ? x : 1.0;
    for (int i = 0; i < 64; i++) g = 0.5 * (g + x / g);
    return g;
}
HDC constexpr int lof(int r) { return r >= 4 ? 2 : (r >= 1 ? 1 : 0); }

HDC constexpr double cg_c(int l1, int m1, int l2, int m2, int l3, int m3) {
    if (m3 != m1 + m2) return 0.0;
    int lmin = (l1 > l2) ? l1 - l2 : l2 - l1;
    if (l3 < lmin || l3 > l1 + l2) return 0.0;
    double pre = csqrt_((2.0 * l3 + 1.0) * cfact(l3 + l1 - l2) * cfact(l3 - l1 + l2) *
                        cfact(l1 + l2 - l3) / cfact(l1 + l2 + l3 + 1));
    pre *= csqrt_(cfact(l3 + m3) * cfact(l3 - m3) * cfact(l1 - m1) * cfact(l1 + m1) *
                  cfact(l2 - m2) * cfact(l2 + m2));
    double s = 0.0;
    for (int k = 0; k <= l1 + l2 - l3; k++) {
        int d2 = l1 - m1 - k, d3 = l2 + m2 - k, d4 = l3 - l2 + m1 + k, d5 = l3 - l1 - m2 + k;
        if (d2 < 0 || d3 < 0 || d4 < 0 || d5 < 0) continue;
        double denom = cfact(k) * cfact(l1 + l2 - l3 - k) * cfact(d2) * cfact(d3) *
                       cfact(d4) * cfact(d5);
        s += ((k & 1) ? -1.0 : 1.0) / denom;
    }
    return pre * s;
}

struct CRow { int n; int col[2]; double re[2]; double im[2]; };

HDC constexpr CRow urow(int r) {
    CRow s{}; int l = lof(r); int base = l * l + l; int mr = r - base;
    const double inv2 = 0.70710678118654752440;
    if (mr == 0) { s.n = 1; s.col[0] = base; s.re[0] = 1.0; s.im[0] = 0.0; }
    else if (mr > 0) {
        int m = mr; double sg = (m & 1) ? -1.0 : 1.0;
        s.n = 2;
        s.col[0] = base - m; s.re[0] = inv2;      s.im[0] = 0.0;
        s.col[1] = base + m; s.re[1] = sg * inv2; s.im[1] = 0.0;
    } else {
        int m = -mr; double sg = (m & 1) ? -1.0 : 1.0;
        s.n = 2;
        s.col[0] = base - m; s.re[0] = 0.0; s.im[0] = inv2;
        s.col[1] = base + m; s.re[1] = 0.0; s.im[1] = -sg * inv2;
    }
    return s;
}

HDC constexpr double real_cg(int o, int i2, int i3) {
    if (((lof(o) + lof(i2) + lof(i3)) & 1) != 0) return 0.0;
    CRow Ua = urow(i2), Ub = urow(i3), Uc = urow(o);
    int la = lof(i2), lb = lof(i3), lc = lof(o);
    int ba = la * la + la, bb = lb * lb + lb, bc = lc * lc + lc;
    double vre = 0.0;
    for (int i = 0; i < Ua.n; i++)
        for (int j = 0; j < Ub.n; j++)
            for (int k = 0; k < Uc.n; k++) {
                double cg = cg_c(la, Ua.col[i] - ba, lb, Ub.col[j] - bb, lc, Uc.col[k] - bc);
                if (cg == 0.0) continue;
                double t1r = Ua.re[i] * Ub.re[j] - Ua.im[i] * Ub.im[j];
                double t1i = Ua.re[i] * Ub.im[j] + Ua.im[i] * Ub.re[j];
                double tre = t1r * Uc.re[k] + t1i * Uc.im[k];
                vre += cg * tre;
            }
    return vre;
}

// ---- register-array contraction: acc[o] += cg * a[i2] * b[i3], fully unrolled ----
template <int LO, int HI>
struct Seg {
    static __device__ __forceinline__ void run(float (&acc)[9], const float (&a)[9],
                                               const float (&b)[9]) {
        if constexpr (HI - LO == 1) {
            constexpr int O = LO / 81, I2 = (LO / 9) % 9, I3 = LO % 9;
            constexpr double v = real_cg(O, I2, I3);
            if constexpr (v > 1e-9 || v < -1e-9) {
                acc[O] = fmaf((float)v, a[I2] * b[I3], acc[O]);
            }
        } else {
            Seg<LO, (LO + HI) / 2>::run(acc, a, b);
            Seg<(LO + HI) / 2, HI>::run(acc, a, b);
        }
    }
};

#define C0(o) ((float)real_cg(o, 0, o))

// ---------------- per-pair setup: blocked GEMM, Wf in registers -----------
__global__ __launch_bounds__(256)
void pair_setup_kernel(const float* __restrict__ r_ij,
                       const float* __restrict__ Wf,
                       const float* __restrict__ bf) {
    __shared__ float s_rad[PCHUNK][NRBF];   // rad * cut; row = 80B, 16B-aligned
    __shared__ float s_cut[PCHUNK];
    __shared__ float s_d[PCHUNK];

    int t = blockIdx.y;
    int p0 = blockIdx.x * PCHUNK;
    int tid = threadIdx.x;
    int f = tid & 63;
    int slot = tid >> 6;

    // preload Wf column f for this t
    float w[NL][NRBF];
    const float* wf = Wf + t * (NRBF * NL * FDIM) + f;
    #pragma unroll
    for (int k = 0; k < NRBF; k++)
        #pragma unroll
        for (int l = 0; l < NL; l++)
            w[l][k] = __ldg(wf + k * NL * FDIM + l * FDIM);
    float bfl[NL];
    #pragma unroll
    for (int l = 0; l < NL; l++) bfl[l] = __ldg(bf + t * NL * FDIM + l * FDIM + f);

    // phase A0: 64 threads compute d + cut (+ Y, only from t==0 blocks)
    if (tid < PCHUNK) {
        int p = p0 + tid;
        if (p < NPAIRS) {
            float rx = __ldg(r_ij + 3 * p), ry = __ldg(r_ij + 3 * p + 1),
                  rz = __ldg(r_ij + 3 * p + 2);
            float d = sqrtf(rx * rx + ry * ry + rz * rz);
            s_d[tid] = d;
            s_cut[tid] = (d < CUTOFF)
                       ? 0.5f * (cosf(d * (3.14159265358979323846f / CUTOFF)) + 1.f) : 0.f;
            if (blockIdx.y == 0) {
                float inv = 1.f / d;
                float x = rx * inv, y = ry * inv, z = rz * inv;
                const float c0 = 0.28209479177387814f;
                const float c1 = 0.4886025119029199f;
                const float c2 = 1.0925484305920792f;
                const float c3 = 0.31539156525252005f;
                const float c4 = 0.5462742152960396f;
                float4* yp = reinterpret_cast<float4*>(g_Y + p * YPAD);
                yp[0] = make_float4(c0, c1 * y, c1 * z, c1 * x);
                yp[1] = make_float4(c2 * x * y, c2 * y * z,
                                    c3 * (3.f * z * z - 1.f), c2 * x * z);
                yp[2] = make_float4(c4 * (x * x - y * y), 0.f, 0.f, 0.f);
            }
        }
    }
    __syncthreads();

    // phase A1: rad*cut table, 64*20 = 1280 items over 256 threads
    const float width = CUTOFF / (NRBF - 1);
    const float alpha = -0.5f / (width * width);
    for (int idx = tid; idx < PCHUNK * NRBF; idx += 256) {
        int pl = idx / NRBF, k = idx % NRBF;
        if (p0 + pl < NPAIRS) {
            float dd = s_d[pl] - width * (float)k;
            s_rad[pl][k] = __expf(alpha * dd * dd) * s_cut[pl];
        }
    }
    __syncthreads();

    // phase B: each slot sweeps 16 pairs; 5 LDS.128 + 60 FMA + 3 STG per pair
    float* wout = g_Wij + ((size_t)t * NPAIRS) * (NL * FDIM) + f;
    for (int pl = slot; pl < PCHUNK; pl += 4) {
        int p = p0 + pl;
        if (p >= NPAIRS) break;
        float cut = s_cut[pl];
        float s0 = bfl[0] * cut, s1 = bfl[1] * cut, s2 = bfl[2] * cut;
        const float4* rp = reinterpret_cast<const float4*>(s_rad[pl]);
        #pragma unroll
        for (int k4 = 0; k4 < 5; k4++) {
            float4 r = rp[k4];
            s0 = fmaf(r.x, w[0][k4 * 4 + 0], s0);
            s1 = fmaf(r.x, w[1][k4 * 4 + 0], s1);
            s2 = fmaf(r.x, w[2][k4 * 4 + 0], s2);
            s0 = fmaf(r.y, w[0][k4 * 4 + 1], s0);
            s1 = fmaf(r.y, w[1][k4 * 4 + 1], s1);
            s2 = fmaf(r.y, w[2][k4 * 4 + 1], s2);
            s0 = fmaf(r.z, w[0][k4 * 4 + 2], s0);
            s1 = fmaf(r.z, w[1][k4 * 4 + 2], s1);
            s2 = fmaf(r.z, w[2][k4 * 4 + 2], s2);
            s0 = fmaf(r.w, w[0][k4 * 4 + 3], s0);
            s1 = fmaf(r.w, w[1][k4 * 4 + 3], s1);
            s2 = fmaf(r.w, w[2][k4 * 4 + 3], s2);
        }
        float* wp = wout + (size_t)p * (NL * FDIM);
        wp[0]   = s0;
        wp[64]  = s1;
        wp[128] = s2;
    }
}

// ---------------- fused message + update: 1 atom per 64-thread block ------
template <bool FIRST>
__global__ __launch_bounds__(64)
void fused_kernel(const int* __restrict__ idx_i, const int* __restrict__ idx_j,
                  const int* __restrict__ Z, const float* __restrict__ emb,
                  float* __restrict__ xout,
                  const float* __restrict__ W1, const float* __restrict__ W2,
                  const float* __restrict__ W3, const float* __restrict__ Wg,
                  const float* __restrict__ bg) {
    constexpr int T = FIRST ? 0 : 1;
    __shared__ float sb0[NSH * FDIM];
    __shared__ float sb1[NSH * FDIM];

    int f = threadIdx.x;
    int a = blockIdx.x;

    int lo = 0, hi = NPAIRS;
    while (lo < hi) { int m = (lo + hi) >> 1; if (idx_i[m] < a) lo = m + 1; else hi = m; }
    int pstart = lo;
    hi = NPAIRS;
    while (lo < hi) { int m = (lo + hi) >> 1; if (idx_i[m] <= a) lo = m + 1; else hi = m; }
    int pend = lo;

    float dxr[9];
    #pragma unroll
    for (int o = 0; o < 9; o++) dxr[o] = 0.f;

    const float* wbase = g_Wij + (size_t)T * NPAIRS * NL * FDIM + f;

    for (int p = pstart; p < pend; p++) {
        int j = __ldg(idx_j + p);
        const float4* yp4 = reinterpret_cast<const float4*>(g_Y + p * YPAD);
        float4 y0 = yp4[0], y1 = yp4[1], y2 = yp4[2];
        const float* wp = wbase + p * (NL * FDIM);
        float w0 = wp[0], w1v = wp[64], w2v = wp[128];
        float tv[9];
        tv[0] = y0.x * w0;
        tv[1] = y0.y * w1v;
        tv[2] = y0.z * w1v;
        tv[3] = y0.w * w1v;
        tv[4] = y1.x * w2v;
        tv[5] = y1.y * w2v;
        tv[6] = y1.z * w2v;
        tv[7] = y1.w * w2v;
        tv[8] = y2.x * w2v;

        if constexpr (FIRST) {
            float x0 = __ldg(emb + __ldg(Z + j) * FDIM + f);
            const float c[9] = {C0(0), C0(1), C0(2), C0(3), C0(4),
                                C0(5), C0(6), C0(7), C0(8)};
            #pragma unroll
            for (int o = 0; o < 9; o++)
                dxr[o] = fmaf(c[o] * x0, tv[o], dxr[o]);
        } else {
            const float* xj = xout + j * (NSH * FDIM) + f;
            float xr[9];
            #pragma unroll
            for (int o = 0; o < 9; o++) xr[o] = __ldg(xj + o * 64);
            Seg<0, 729>::run(dxr, xr, tv);
        }
    }

    const float* w1 = W1 + T * 4096 + f;
    const float* w2 = W2 + T * 4096 + f;
    const float* w3 = W3 + T * 4096 + f;
    const float* wg = Wg + T * 12288 + f;
    const float* bgp = bg + T * 192 + f;
    int base = a * (NSH * FDIM);

    #pragma unroll
    for (int o = 0; o < 9; o++) sb0[o * 64 + f] = dxr[o];

    float w[64];
    #pragma unroll
    for (int k = 0; k < 64; k++) w[k] = __ldg(w1 + k * 64);
    __syncthreads();

    float ddx[9];
    const float4* a0p = reinterpret_cast<const float4*>(sb0);
    #pragma unroll
    for (int o = 0; o < 9; o++) {
        float s = 0.f;
        #pragma unroll
        for (int k4 = 0; k4 < 16; k4++) {
            float4 v = a0p[o * 16 + k4];
            s = fmaf(v.x, w[k4 * 4 + 0], s);
            s = fmaf(v.y, w[k4 * 4 + 1], s);
            s = fmaf(v.z, w[k4 * 4 + 2], s);
            s = fmaf(v.w, w[k4 * 4 + 3], s);
        }
        ddx[o] = s;
    }

    float tp[9];
    #pragma unroll
    for (int o = 0; o < 9; o++) tp[o] = dxr[o];
    Seg<0, 729>::run(tp, dxr, ddx);

    #pragma unroll
    for (int o = 0; o < 9; o++) sb1[o * 64 + f] = tp[o];

    #pragma unroll
    for (int k = 0; k < 64; k++) w[k] = __ldg(w2 + k * 64);
    __syncthreads();

    float dx2[9];
    const float4* a1p = reinterpret_cast<const float4*>(sb1);
    #pragma unroll
    for (int o = 0; o < 9; o++) {
        float s = 0.f;
        #pragma unroll
        for (int k4 = 0; k4 < 16; k4++) {
            float4 v = a1p[o * 16 + k4];
            s = fmaf(v.x, w[k4 * 4 + 0], s);
            s = fmaf(v.y, w[k4 * 4 + 1], s);
            s = fmaf(v.z, w[k4 * 4 + 2], s);
            s = fmaf(v.w, w[k4 * 4 + 3], s);
        }
        dx2[o] = s;
    }
    sb0[f] = dx2[0];
    __syncthreads();

    float g0 = bgp[0], g1 = bgp[64], g2 = bgp[128];
    {
        const float4* r0 = reinterpret_cast<const float4*>(sb0);
        #pragma unroll
        for (int k4 = 0; k4 < 16; k4++) {
            float4 v = r0[k4];
            const float* wgk = wg + (k4 * 4) * 192;
            g0 = fmaf(v.x, __ldg(wgk), g0);
            g1 = fmaf(v.x, __ldg(wgk + 64), g1);
            g2 = fmaf(v.x, __ldg(wgk + 128), g2);
            g0 = fmaf(v.y, __ldg(wgk + 192), g0);
            g1 = fmaf(v.y, __ldg(wgk + 256), g1);
            g2 = fmaf(v.y, __ldg(wgk + 320), g2);
            g0 = fmaf(v.z, __ldg(wgk + 384), g0);
            g1 = fmaf(v.z, __ldg(wgk + 448), g1);
            g2 = fmaf(v.z, __ldg(wgk + 512), g2);
            g0 = fmaf(v.w, __ldg(wgk + 576), g0);
            g1 = fmaf(v.w, __ldg(wgk + 640), g1);
            g2 = fmaf(v.w, __ldg(wgk + 704), g2);
        }
    }
    float sg[3];
    sg[0] = 1.f / (1.f + __expf(-g0));
    sg[1] = 1.f / (1.f + __expf(-g1));
    sg[2] = 1.f / (1.f + __expf(-g2));

    #pragma unroll
    for (int o = 0; o < 9; o++) {
        int l = (o >= 4) ? 2 : ((o >= 1) ? 1 : 0);
        sb1[o * 64 + f] = dx2[o] * sg[l];
    }

    #pragma unroll
    for (int k = 0; k < 64; k++) w[k] = __ldg(w3 + k * 64);
    __syncthreads();

    #pragma unroll
    for (int o = 0; o < 9; o++) {
        float s = 0.f;
        #pragma unroll
        for (int k4 = 0; k4 < 16; k4++) {
            float4 v = a1p[o * 16 + k4];
            s = fmaf(v.x, w[k4 * 4 + 0], s);
            s = fmaf(v.y, w[k4 * 4 + 1], s);
            s = fmaf(v.z, w[k4 * 4 + 2], s);
            s = fmaf(v.w, w[k4 * 4 + 3], s);
        }
        float prev;
        if constexpr (FIRST) {
            prev = (o == 0) ? __ldg(emb + __ldg(Z + a) * FDIM + f) : 0.f;
        } else {
            prev = xout[base + o * 64 + f];
        }
        xout[base + o * 64 + f] = prev + s;
    }
}

// ---------------- launch ---------------------------------------------------
extern "C" void kernel_launch(void* const* d_in, const int* in_sizes, int n_in,
                              void* d_out, int out_size) {
    const int*   Z    = (const int*)d_in[0];
    const float* r_ij = (const float*)d_in[1];
    const int*   idxi = (const int*)d_in[2];
    const int*   idxj = (const int*)d_in[3];
    const float* emb  = (const float*)d_in[4];
    const float* Wf   = (const float*)d_in[5];
    const float* bf   = (const float*)d_in[6];
    const float* W1   = (const float*)d_in[7];
    const float* W2   = (const float*)d_in[8];
    const float* W3   = (const float*)d_in[9];
    const float* Wg   = (const float*)d_in[10];
    const float* bg   = (const float*)d_in[11];
    float* xout = (float*)d_out;

    dim3 psgrid((NPAIRS + PCHUNK - 1) / PCHUNK, NITER);
    pair_setup_kernel<<<psgrid, 256>>>(r_ij, Wf, bf);
    fused_kernel<true ><<<NATOMS, 64>>>(idxi, idxj, Z, emb, xout,
                                        W1, W2, W3, Wg, bg);
    fused_kernel<false><<<NATOMS, 64>>>(idxi, idxj, Z, emb, xout,
                                        W1, W2, W3, Wg, bg);
}

// round 10
// speedup vs baseline: 4.2500x; 1.0133x over previous
#include <cuda_runtime.h>
#include <math.h>

#define NATOMS 1000
#define NPAIRS 10000
#define FDIM   64
#define NSH    9
#define NL     3
#define NRBF   20
#define CUTOFF 5.0f
#define CH     32

#define HDC __host__ __device__

// ---------------- device scratch: x after iteration 0 (no allocations) ----
__device__ float g_x1[NATOMS * NSH * FDIM];

// =================== compile-time real Clebsch-Gordan table ===============
HDC constexpr double cfact(int n) { double r = 1; for (int i = 2; i <= n; i++) r *= i; return r; }
HDC constexpr double csqrt_(double x) {
    if (x <= 0.0) return 0.0;
    double g = (x > 1.0) ? x : 1.0;
    for (int i = 0; i < 64; i++) g = 0.5 * (g + x / g);
    return g;
}
HDC constexpr int lof(int r) { return r >= 4 ? 2 : (r >= 1 ? 1 : 0); }

HDC constexpr double cg_c(int l1, int m1, int l2, int m2, int l3, int m3) {
    if (m3 != m1 + m2) return 0.0;
    int lmin = (l1 > l2) ? l1 - l2 : l2 - l1;
    if (l3 < lmin || l3 > l1 + l2) return 0.0;
    double pre = csqrt_((2.0 * l3 + 1.0) * cfact(l3 + l1 - l2) * cfact(l3 - l1 + l2) *
                        cfact(l1 + l2 - l3) / cfact(l1 + l2 + l3 + 1));
    pre *= csqrt_(cfact(l3 + m3) * cfact(l3 - m3) * cfact(l1 - m1) * cfact(l1 + m1) *
                  cfact(l2 - m2) * cfact(l2 + m2));
    double s = 0.0;
    for (int k = 0; k <= l1 + l2 - l3; k++) {
        int d2 = l1 - m1 - k, d3 = l2 + m2 - k, d4 = l3 - l2 + m1 + k, d5 = l3 - l1 - m2 + k;
        if (d2 < 0 || d3 < 0 || d4 < 0 || d5 < 0) continue;
        double denom = cfact(k) * cfact(l1 + l2 - l3 - k) * cfact(d2) * cfact(d3) *
                       cfact(d4) * cfact(d5);
        s += ((k & 1) ? -1.0 : 1.0) / denom;
    }
    return pre * s;
}

struct CRow { int n; int col[2]; double re[2]; double im[2]; };

HDC constexpr CRow urow(int r) {
    CRow s{}; int l = lof(r); int base = l * l + l; int mr = r - base;
    const double inv2 = 0.70710678118654752440;
    if (mr == 0) { s.n = 1; s.col[0] = base; s.re[0] = 1.0; s.im[0] = 0.0; }
    else if (mr > 0) {
        int m = mr; double sg = (m & 1) ? -1.0 : 1.0;
        s.n = 2;
        s.col[0] = base - m; s.re[0] = inv2;      s.im[0] = 0.0;
        s.col[1] = base + m; s.re[1] = sg * inv2; s.im[1] = 0.0;
    } else {
        int m = -mr; double sg = (m & 1) ? -1.0 : 1.0;
        s.n = 2;
        s.col[0] = base - m; s.re[0] = 0.0; s.im[0] = inv2;
        s.col[1] = base + m; s.re[1] = 0.0; s.im[1] = -sg * inv2;
    }
    return s;
}

HDC constexpr double real_cg(int o, int i2, int i3) {
    if (((lof(o) + lof(i2) + lof(i3)) & 1) != 0) return 0.0;
    CRow Ua = urow(i2), Ub = urow(i3), Uc = urow(o);
    int la = lof(i2), lb = lof(i3), lc = lof(o);
    int ba = la * la + la, bb = lb * lb + lb, bc = lc * lc + lc;
    double vre = 0.0;
    for (int i = 0; i < Ua.n; i++)
        for (int j = 0; j < Ub.n; j++)
            for (int k = 0; k < Uc.n; k++) {
                double cg = cg_c(la, Ua.col[i] - ba, lb, Ub.col[j] - bb, lc, Uc.col[k] - bc);
                if (cg == 0.0) continue;
                double t1r = Ua.re[i] * Ub.re[j] - Ua.im[i] * Ub.im[j];
                double t1i = Ua.re[i] * Ub.im[j] + Ua.im[i] * Ub.re[j];
                double tre = t1r * Uc.re[k] + t1i * Uc.im[k];
                vre += cg * tre;
            }
    return vre;
}

// ---- register-array contraction: acc[o] += cg * a[i2] * b[i3], fully unrolled ----
template <int LO, int HI>
struct Seg {
    static __device__ __forceinline__ void run(float (&acc)[9], const float (&a)[9],
                                               const float (&b)[9]) {
        if constexpr (HI - LO == 1) {
            constexpr int O = LO / 81, I2 = (LO / 9) % 9, I3 = LO % 9;
            constexpr double v = real_cg(O, I2, I3);
            if constexpr (v > 1e-9 || v < -1e-9) {
                acc[O] = fmaf((float)v, a[I2] * b[I3], acc[O]);
            }
        } else {
            Seg<LO, (LO + HI) / 2>::run(acc, a, b);
            Seg<(LO + HI) / 2, HI>::run(acc, a, b);
        }
    }
};

#define C0(o) ((float)real_cg(o, 0, o))

// ---------------- fused filter + message + update: 1 atom / 64-thread block ----
// FIRST:  reads emb[Z] (iteration-0 x), writes x1 -> g_x1
// !FIRST: reads g_x1, writes final x -> xw (d_out)
template <bool FIRST>
__global__ __launch_bounds__(64)
void fused_kernel(const int* __restrict__ idx_i, const int* __restrict__ idx_j,
                  const int* __restrict__ Z, const float* __restrict__ emb,
                  const float* __restrict__ r_ij,
                  const float* __restrict__ Wf, const float* __restrict__ bfv,
                  const float* __restrict__ xin, float* __restrict__ xw,
                  const float* __restrict__ W1, const float* __restrict__ W2,
                  const float* __restrict__ W3, const float* __restrict__ Wg,
                  const float* __restrict__ bg) {
    constexpr int T = FIRST ? 0 : 1;
    __shared__ float s_rad[CH][NRBF];   // rad * cut
    __shared__ float s_cut[CH];
    __shared__ float s_Y[CH][12];
    __shared__ int   s_j[CH];           // FIRST: Z[idx_j[p]]; else idx_j[p]
    __shared__ float sb0[NSH * FDIM];
    __shared__ float sb1[NSH * FDIM];

    int f = threadIdx.x;
    int a = blockIdx.x;

    // segment of sorted idx_i equal to a
    int lo = 0, hi = NPAIRS;
    while (lo < hi) { int m = (lo + hi) >> 1; if (idx_i[m] < a) lo = m + 1; else hi = m; }
    int pstart = lo;
    hi = NPAIRS;
    while (lo < hi) { int m = (lo + hi) >> 1; if (idx_i[m] <= a) lo = m + 1; else hi = m; }
    int pend = lo;

    // preload Wf column f (this t) + bias
    float wfr[NL][NRBF];
    {
        const float* wf = Wf + T * (NRBF * NL * FDIM) + f;
        #pragma unroll
        for (int k = 0; k < NRBF; k++)
            #pragma unroll
            for (int l = 0; l < NL; l++)
                wfr[l][k] = __ldg(wf + k * NL * FDIM + l * FDIM);
    }
    float bfl[NL];
    #pragma unroll
    for (int l = 0; l < NL; l++) bfl[l] = __ldg(bfv + T * NL * FDIM + l * FDIM + f);

    float dxr[9];
    #pragma unroll
    for (int o = 0; o < 9; o++) dxr[o] = 0.f;

    const float width = CUTOFF / (NRBF - 1);
    const float alpha = -0.5f / (width * width);

    for (int c = pstart; c < pend; c += CH) {
        int n = min(CH, pend - c);
        if (f < n) {
            int p = c + f;
            int jj = __ldg(idx_j + p);
            s_j[f] = FIRST ? __ldg(Z + jj) : jj;
            float rx = __ldg(r_ij + 3 * p), ry = __ldg(r_ij + 3 * p + 1),
                  rz = __ldg(r_ij + 3 * p + 2);
            float d = sqrtf(rx * rx + ry * ry + rz * rz);
            float cut = (d < CUTOFF)
                      ? 0.5f * (cosf(d * (3.14159265358979323846f / CUTOFF)) + 1.f) : 0.f;
            s_cut[f] = cut;
            #pragma unroll
            for (int k = 0; k < NRBF; k++) {
                float dd = d - width * (float)k;
                s_rad[f][k] = __expf(alpha * dd * dd) * cut;
            }
            float inv = 1.f / d;
            float x = rx * inv, y = ry * inv, z = rz * inv;
            const float c0 = 0.28209479177387814f;
            const float c1 = 0.4886025119029199f;
            const float c2 = 1.0925484305920792f;
            const float c3 = 0.31539156525252005f;
            const float c4 = 0.5462742152960396f;
            s_Y[f][0] = c0;
            s_Y[f][1] = c1 * y;
            s_Y[f][2] = c1 * z;
            s_Y[f][3] = c1 * x;
            s_Y[f][4] = c2 * x * y;
            s_Y[f][5] = c2 * y * z;
            s_Y[f][6] = c3 * (3.f * z * z - 1.f);
            s_Y[f][7] = c2 * x * z;
            s_Y[f][8] = c4 * (x * x - y * y);
        }
        __syncthreads();

        for (int i = 0; i < n; i++) {
            float cut = s_cut[i];
            float w0 = bfl[0] * cut, w1v = bfl[1] * cut, w2v = bfl[2] * cut;
            #pragma unroll
            for (int k = 0; k < NRBF; k++) {
                float r = s_rad[i][k];
                w0  = fmaf(r, wfr[0][k], w0);
                w1v = fmaf(r, wfr[1][k], w1v);
                w2v = fmaf(r, wfr[2][k], w2v);
            }
            float tv[9];
            tv[0] = s_Y[i][0] * w0;
            tv[1] = s_Y[i][1] * w1v;
            tv[2] = s_Y[i][2] * w1v;
            tv[3] = s_Y[i][3] * w1v;
            tv[4] = s_Y[i][4] * w2v;
            tv[5] = s_Y[i][5] * w2v;
            tv[6] = s_Y[i][6] * w2v;
            tv[7] = s_Y[i][7] * w2v;
            tv[8] = s_Y[i][8] * w2v;

            if constexpr (FIRST) {
                float x0 = __ldg(emb + s_j[i] * FDIM + f);
                const float cc[9] = {C0(0), C0(1), C0(2), C0(3), C0(4),
                                     C0(5), C0(6), C0(7), C0(8)};
                #pragma unroll
                for (int o = 0; o < 9; o++)
                    dxr[o] = fmaf(cc[o] * x0, tv[o], dxr[o]);
            } else {
                const float* xj = xin + s_j[i] * (NSH * FDIM) + f;
                float xr[9];
                #pragma unroll
                for (int o = 0; o < 9; o++) xr[o] = __ldg(xj + o * 64);
                Seg<0, 729>::run(dxr, xr, tv);
            }
        }
        __syncthreads();
    }

    // ---- update stage ----
    const float* w1 = W1 + T * 4096 + f;
    const float* w2 = W2 + T * 4096 + f;
    const float* w3 = W3 + T * 4096 + f;
    const float* wg = Wg + T * 12288 + f;
    const float* bgp = bg + T * 192 + f;
    int base = a * (NSH * FDIM);

    #pragma unroll
    for (int o = 0; o < 9; o++) sb0[o * 64 + f] = dxr[o];

    float w[64];
    #pragma unroll
    for (int k = 0; k < 64; k++) w[k] = __ldg(w1 + k * 64);
    __syncthreads();

    float ddx[9];
    const float4* a0p = reinterpret_cast<const float4*>(sb0);
    #pragma unroll
    for (int o = 0; o < 9; o++) {
        float s = 0.f;
        #pragma unroll
        for (int k4 = 0; k4 < 16; k4++) {
            float4 v = a0p[o * 16 + k4];
            s = fmaf(v.x, w[k4 * 4 + 0], s);
            s = fmaf(v.y, w[k4 * 4 + 1], s);
            s = fmaf(v.z, w[k4 * 4 + 2], s);
            s = fmaf(v.w, w[k4 * 4 + 3], s);
        }
        ddx[o] = s;
    }

    float tp[9];
    #pragma unroll
    for (int o = 0; o < 9; o++) tp[o] = dxr[o];
    Seg<0, 729>::run(tp, dxr, ddx);

    #pragma unroll
    for (int o = 0; o < 9; o++) sb1[o * 64 + f] = tp[o];

    #pragma unroll
    for (int k = 0; k < 64; k++) w[k] = __ldg(w2 + k * 64);
    __syncthreads();

    float dx2[9];
    const float4* a1p = reinterpret_cast<const float4*>(sb1);
    #pragma unroll
    for (int o = 0; o < 9; o++) {
        float s = 0.f;
        #pragma unroll
        for (int k4 = 0; k4 < 16; k4++) {
            float4 v = a1p[o * 16 + k4];
            s = fmaf(v.x, w[k4 * 4 + 0], s);
            s = fmaf(v.y, w[k4 * 4 + 1], s);
            s = fmaf(v.z, w[k4 * 4 + 2], s);
            s = fmaf(v.w, w[k4 * 4 + 3], s);
        }
        dx2[o] = s;
    }
    sb0[f] = dx2[0];
    __syncthreads();

    float g0 = bgp[0], g1 = bgp[64], g2 = bgp[128];
    {
        const float4* r0 = reinterpret_cast<const float4*>(sb0);
        #pragma unroll
        for (int k4 = 0; k4 < 16; k4++) {
            float4 v = r0[k4];
            const float* wgk = wg + (k4 * 4) * 192;
            g0 = fmaf(v.x, __ldg(wgk), g0);
            g1 = fmaf(v.x, __ldg(wgk + 64), g1);
            g2 = fmaf(v.x, __ldg(wgk + 128), g2);
            g0 = fmaf(v.y, __ldg(wgk + 192), g0);
            g1 = fmaf(v.y, __ldg(wgk + 256), g1);
            g2 = fmaf(v.y, __ldg(wgk + 320), g2);
            g0 = fmaf(v.z, __ldg(wgk + 384), g0);
            g1 = fmaf(v.z, __ldg(wgk + 448), g1);
            g2 = fmaf(v.z, __ldg(wgk + 512), g2);
            g0 = fmaf(v.w, __ldg(wgk + 576), g0);
            g1 = fmaf(v.w, __ldg(wgk + 640), g1);
            g2 = fmaf(v.w, __ldg(wgk + 704), g2);
        }
    }
    float sg[3];
    sg[0] = 1.f / (1.f + __expf(-g0));
    sg[1] = 1.f / (1.f + __expf(-g1));
    sg[2] = 1.f / (1.f + __expf(-g2));

    #pragma unroll
    for (int o = 0; o < 9; o++) {
        int l = (o >= 4) ? 2 : ((o >= 1) ? 1 : 0);
        sb1[o * 64 + f] = dx2[o] * sg[l];
    }

    #pragma unroll
    for (int k = 0; k < 64; k++) w[k] = __ldg(w3 + k * 64);
    __syncthreads();

    #pragma unroll
    for (int o = 0; o < 9; o++) {
        float s = 0.f;
        #pragma unroll
        for (int k4 = 0; k4 < 16; k4++) {
            float4 v = a1p[o * 16 + k4];
            s = fmaf(v.x, w[k4 * 4 + 0], s);
            s = fmaf(v.y, w[k4 * 4 + 1], s);
            s = fmaf(v.z, w[k4 * 4 + 2], s);
            s = fmaf(v.w, w[k4 * 4 + 3], s);
        }
        float prev;
        if constexpr (FIRST) {
            prev = (o == 0) ? __ldg(emb + __ldg(Z + a) * FDIM + f) : 0.f;
        } else {
            prev = __ldg(xin + base + o * 64 + f);
        }
        xw[base + o * 64 + f] = prev + s;
    }
}

// ---------------- launch ---------------------------------------------------
extern "C" void kernel_launch(void* const* d_in, const int* in_sizes, int n_in,
                              void* d_out, int out_size) {
    const int*   Z    = (const int*)d_in[0];
    const float* r_ij = (const float*)d_in[1];
    const int*   idxi = (const int*)d_in[2];
    const int*   idxj = (const int*)d_in[3];
    const float* emb  = (const float*)d_in[4];
    const float* Wf   = (const float*)d_in[5];
    const float* bf   = (const float*)d_in[6];
    const float* W1   = (const float*)d_in[7];
    const float* W2   = (const float*)d_in[8];
    const float* W3   = (const float*)d_in[9];
    const float* Wg   = (const float*)d_in[10];
    const float* bg   = (const float*)d_in[11];
    float* xout = (float*)d_out;

    float* x1;
    cudaGetSymbolAddress((void**)&x1, g_x1);

    // iter 0: emb -> g_x1 ; iter 1: g_x1 -> xout (no cross-launch aliasing)
    fused_kernel<true ><<<NATOMS, 64>>>(idxi, idxj, Z, emb, r_ij, Wf, bf,
                                        nullptr, x1, W1, W2, W3, Wg, bg);
    fused_kernel<false><<<NATOMS, 64>>>(idxi, idxj, Z, emb, r_ij, Wf, bf,
                                        x1, xout, W1, W2, W3, Wg, bg);
}